// round 13
// baseline (speedup 1.0000x reference)
#include <cuda_runtime.h>
#include <cuda_fp16.h>
#include <math.h>
#include <stdint.h>

#define BATCH 32
#define D_IN  512
#define T_LEN 1024
#define D_MOD 1024
#define M_LEN 1023

#define SE_C (-8.99447308311468881e-03f)   // -ln(10000)/1024

typedef __half hlf;

// ---------------------------------------------------------------------------
// Scratch (allocation-free rule: __device__ globals), fp16 hi/lo planes
// ---------------------------------------------------------------------------
__device__ hlf g_Xh[(size_t)BATCH * D_IN * T_LEN];
__device__ hlf g_Xl[(size_t)BATCH * D_IN * T_LEN];
__device__ hlf g_WA2h[2048 * D_MOD];                  // rows 0-1023 W_KQ, 1024-2047 W_PV
__device__ hlf g_WA2l[2048 * D_MOD];
__device__ hlf g_BW2h[D_MOD * 2048];                  // cols: [Wem | SE | W_un^T]
__device__ hlf g_BW2l[D_MOD * 2048];
__device__ hlf g_LLh[(size_t)2048 * 1536];            // [O1top = Wke|KSE ; H = Wpv@BW]
__device__ hlf g_LLl[(size_t)2048 * 1536];
__device__ hlf g_O2h[1536 * 1536];                    // [Mw|P ; Q|V4]
__device__ hlf g_O2l[1536 * 1536];
__device__ hlf g_O1bh[512 * 1536];                    // [WcW | WcSE]
__device__ hlf g_O1bl[512 * 1536];
__device__ hlf g_URh[(size_t)BATCH * 1536 * T_LEN];   // per batch: rows 0-511 U', 512-1535 R
__device__ hlf g_URl[(size_t)BATCH * 1536 * T_LEN];
__device__ hlf g_Zh[(size_t)BATCH * D_IN * T_LEN];
__device__ hlf g_Zl[(size_t)BATCH * D_IN * T_LEN];
__device__ hlf g_Sh[(size_t)BATCH * D_MOD * T_LEN];   // softmax (single plane, row 1023 = 0)

// ---------------------------------------------------------------------------
// Helpers
// ---------------------------------------------------------------------------
__device__ __forceinline__ uint32_t smem_u32(const void* p) {
    uint32_t a;
    asm("{ .reg .u64 t; cvta.to.shared.u64 t, %1; cvt.u32.u64 %0, t; }" : "=r"(a) : "l"(p));
    return a;
}
__device__ __forceinline__ void ldsm4(uint32_t* r, uint32_t addr) {
    asm volatile("ldmatrix.sync.aligned.m8n8.x4.shared.b16 {%0,%1,%2,%3}, [%4];"
        : "=r"(r[0]), "=r"(r[1]), "=r"(r[2]), "=r"(r[3]) : "r"(addr));
}
__device__ __forceinline__ void ldsm4t(uint32_t* r, uint32_t addr) {
    asm volatile("ldmatrix.sync.aligned.m8n8.x4.trans.shared.b16 {%0,%1,%2,%3}, [%4];"
        : "=r"(r[0]), "=r"(r[1]), "=r"(r[2]), "=r"(r[3]) : "r"(addr));
}
__device__ __forceinline__ void mma16816(float* d, const uint32_t* a, const uint32_t* b) {
    asm volatile("mma.sync.aligned.m16n8k16.row.col.f32.f16.f16.f32 "
        "{%0,%1,%2,%3}, {%4,%5,%6,%7}, {%8,%9}, {%0,%1,%2,%3};"
        : "+f"(d[0]), "+f"(d[1]), "+f"(d[2]), "+f"(d[3])
        : "r"(a[0]), "r"(a[1]), "r"(a[2]), "r"(a[3]), "r"(b[0]), "r"(b[1]));
}
__device__ __forceinline__ void cpa16(uint32_t dst, const void* src) {
    asm volatile("cp.async.cg.shared.global [%0], [%1], 16;" :: "r"(dst), "l"(src));
}
__device__ __forceinline__ void cpa_commit() {
    asm volatile("cp.async.commit_group;" ::: "memory");
}
template<int N>
__device__ __forceinline__ void cpa_wait() {
    asm volatile("cp.async.wait_group %0;" :: "n"(N) : "memory");
}
__device__ __forceinline__ uint32_t pack2(hlf a, hlf b) {
    __half2 t = __halves2half2(a, b);
    return *reinterpret_cast<uint32_t*>(&t);
}
__device__ __forceinline__ void split1(float x, hlf& h, hlf& l) {
    h = __float2half(x);
    l = __float2half(x - __half2float(h));
}

// ---------------------------------------------------------------------------
// Conversions
// ---------------------------------------------------------------------------
__global__ void conv_xs(const float4* __restrict__ in,
                        hlf* __restrict__ oh, hlf* __restrict__ ol, size_t n4) {
    size_t i = (size_t)blockIdx.x * blockDim.x + threadIdx.x;
    if (i >= n4) return;
    float4 v = in[i];
    hlf h0,h1,h2,h3,l0,l1,l2,l3;
    split1(v.x,h0,l0); split1(v.y,h1,l1); split1(v.z,h2,l2); split1(v.w,h3,l3);
    *(uint2*)(oh + 4*i) = make_uint2(pack2(h0,h1), pack2(h2,h3));
    *(uint2*)(ol + 4*i) = make_uint2(pack2(l0,l1), pack2(l2,l3));
}

// y=0: W_KQ -> WA2 rows 0-1023; y=1: W_PV -> WA2 rows 1024-2047;
// y=2: W_embed -> BW2 cols 0-511 (ld 2048)
__global__ void conv_w(const float4* __restrict__ wkq, const float4* __restrict__ wpv,
                       const float4* __restrict__ wem,
                       hlf* __restrict__ WAh, hlf* __restrict__ WAl,
                       hlf* __restrict__ BWh, hlf* __restrict__ BWl) {
    int y = blockIdx.y;
    int i = blockIdx.x * 256 + threadIdx.x;
    float4 v; hlf h0,h1,h2,h3,l0,l1,l2,l3;
    if (y == 0) {
        if (i >= 262144) return;
        v = wkq[i];
        split1(v.x,h0,l0); split1(v.y,h1,l1); split1(v.z,h2,l2); split1(v.w,h3,l3);
        *(uint2*)(WAh + 4*(size_t)i) = make_uint2(pack2(h0,h1), pack2(h2,h3));
        *(uint2*)(WAl + 4*(size_t)i) = make_uint2(pack2(l0,l1), pack2(l2,l3));
    } else if (y == 1) {
        if (i >= 262144) return;
        v = wpv[i];
        split1(v.x,h0,l0); split1(v.y,h1,l1); split1(v.z,h2,l2); split1(v.w,h3,l3);
        size_t off = (size_t)1024 * 1024 + 4*(size_t)i;
        *(uint2*)(WAh + off) = make_uint2(pack2(h0,h1), pack2(h2,h3));
        *(uint2*)(WAl + off) = make_uint2(pack2(l0,l1), pack2(l2,l3));
    } else {
        if (i >= 131072) return;
        v = wem[i];
        split1(v.x,h0,l0); split1(v.y,h1,l1); split1(v.z,h2,l2); split1(v.w,h3,l3);
        int r = i >> 7, c = (i & 127) * 4;
        size_t off = (size_t)r * 2048 + c;
        *(uint2*)(BWh + off) = make_uint2(pack2(h0,h1), pack2(h2,h3));
        *(uint2*)(BWl + off) = make_uint2(pack2(l0,l1), pack2(l2,l3));
    }
}

// W_un [512,1024] -> transposed planes into BW2 cols 1536-2047 (ld 2048)
__global__ void tr_wun(const float* __restrict__ wun,
                       hlf* __restrict__ BWh, hlf* __restrict__ BWl) {
    __shared__ float t[32][33];
    int c0 = blockIdx.x * 32;   // k block (cols of wun)
    int r0 = blockIdx.y * 32;   // m block (rows of wun)
    int tx = threadIdx.x, ty = threadIdx.y;
#pragma unroll
    for (int i = 0; i < 4; i++)
        t[ty + 8 * i][tx] = wun[(size_t)(r0 + ty + 8 * i) * 1024 + c0 + tx];
    __syncthreads();
#pragma unroll
    for (int i = 0; i < 4; i++) {
        int j = ty + 8 * i;
        float v = t[tx][j];               // wun[r0+tx][c0+j]
        hlf h, l; split1(v, h, l);
        size_t off = (size_t)(c0 + j) * 2048 + 1536 + r0 + tx;
        BWh[off] = h; BWl[off] = l;
    }
}

// SE planes -> BW2 cols 512-1535 (ld 2048)
__global__ void se_init(hlf* __restrict__ BWh, hlf* __restrict__ BWl) {
    int idx = blockIdx.x * 256 + threadIdx.x;
    int r = idx >> 10, c = idx & 1023;
    float freq = expf((float)(r & ~1) * SE_C);
    float ang  = (float)c * freq;
    float v = (r & 1) ? cosf(ang) : sinf(ang);
    hlf h, l; split1(v, h, l);
    size_t off = (size_t)r * 2048 + 512 + c;
    BWh[off] = h; BWl[off] = l;
}

// ---------------------------------------------------------------------------
// MMA GEMM, fp16 planes, cp.async 3-stage pipeline, BK=64.
//   TERMS: 1 -> Ah*Bh;  2 -> + Ah*Bl;  3 -> + Al*Bh
//   TA=false: A [M,K]; TA=true: A [K,M]. B always [K,N].
//   ADD: 0 none, 2 += bias[r], 3 += (auxH+auxL)[r*ldaux+c]
//   PLANES: true -> CH/CL fp16 planes; false -> Cf fp32
//   DUAL: blocks with m0 >= Msplit use B2/C2, storing rows rebased to Msplit
// CTA 128x128, 512 threads, 16 warps (4x4), warp tile 32x32.
// ---------------------------------------------------------------------------
#define NT 512

template<bool TA, int ADD, bool PLANES, int TERMS, bool DUAL>
__global__ __launch_bounds__(NT, 1)
void mma_gemm(const hlf* __restrict__ AH, const hlf* __restrict__ AL,
              const hlf* BH, const hlf* BL,
              float* __restrict__ Cf, hlf* CH, hlf* CL,
              const float* __restrict__ bias,
              const hlf* __restrict__ auxH, const hlf* __restrict__ auxL,
              int ldaux, size_t sAux,
              const hlf* B2H, const hlf* B2L, hlf* C2H, hlf* C2L, int Msplit,
              int K, int lda, int ldb, int ldc, int Mstore,
              size_t sA, size_t sB, size_t sC)
{
    constexpr int APL = TA ? (64 * 272) : (128 * 144);
    constexpr int BPL = 64 * 272;
    constexpr int SSZ = 2 * APL + 2 * BPL;
    extern __shared__ char smem[];

    const int tid = threadIdx.x, lane = tid & 31, wid = tid >> 5;
    const int wm = wid >> 2, wn = wid & 3;
    const int m0 = blockIdx.y * 128, n0 = blockIdx.x * 128, bz = blockIdx.z;
    AH += sA * (size_t)bz; AL += sA * (size_t)bz;
    BH += sB * (size_t)bz; BL += sB * (size_t)bz;
    int mofs = 0;
    if (DUAL && m0 >= Msplit) {
        BH = B2H; BL = B2L; CH = C2H; CL = C2L; mofs = Msplit;
    }
    const uint32_t sm = smem_u32(smem);

    float acc[2][4][4];
#pragma unroll
    for (int i = 0; i < 2; i++)
#pragma unroll
        for (int j = 0; j < 4; j++)
#pragma unroll
            for (int e = 0; e < 4; e++) acc[i][j][e] = 0.0f;

    auto issue = [&](int kc, int st) {
        uint32_t sb = sm + st * SSZ;
        int k0 = kc * 64;
        if (!TA) {
#pragma unroll
            for (int it = 0; it < 2; it++) {
                int idx = tid + it * NT;
                int r = idx >> 3, c = idx & 7;
                size_t go = (size_t)(m0 + r) * lda + k0 + c * 8;
                uint32_t so = sb + r * 144 + c * 16;
                cpa16(so, AH + go);
                if (TERMS >= 3) cpa16(so + APL, AL + go);
            }
        } else {
#pragma unroll
            for (int it = 0; it < 2; it++) {
                int idx = tid + it * NT;
                int r = idx >> 4, c = idx & 15;
                size_t go = (size_t)(k0 + r) * lda + m0 + c * 8;
                uint32_t so = sb + r * 272 + c * 16;
                cpa16(so, AH + go);
                if (TERMS >= 3) cpa16(so + APL, AL + go);
            }
        }
#pragma unroll
        for (int it = 0; it < 2; it++) {
            int idx = tid + it * NT;
            int r = idx >> 4, c = idx & 15;
            size_t go = (size_t)(k0 + r) * ldb + n0 + c * 8;
            uint32_t so = sb + 2 * APL + r * 272 + c * 16;
            cpa16(so, BH + go);
            if (TERMS >= 2) cpa16(so + BPL, BL + go);
        }
    };

    auto compute = [&](int st) {
        uint32_t sb = sm + st * SSZ;
#pragma unroll
        for (int ks = 0; ks < 4; ks++) {
            uint32_t ah[2][4], al[2][4], bh[4][2], bl[4][2];
#pragma unroll
            for (int j2 = 0; j2 < 2; j2++) {
                uint32_t addr = sb + 2 * APL + (uint32_t)((ks * 16 + (lane & 15)) * 272
                              + (wn * 32 + j2 * 16 + (lane >> 4) * 8) * 2);
                uint32_t t[4];
                ldsm4t(t, addr);
                bh[j2*2][0]=t[0]; bh[j2*2][1]=t[1]; bh[j2*2+1][0]=t[2]; bh[j2*2+1][1]=t[3];
                if (TERMS >= 2) {
                    ldsm4t(t, addr + BPL);
                    bl[j2*2][0]=t[0]; bl[j2*2][1]=t[1]; bl[j2*2+1][0]=t[2]; bl[j2*2+1][1]=t[3];
                }
            }
#pragma unroll
            for (int i = 0; i < 2; i++) {
                if (!TA) {
                    uint32_t addr = sb + (uint32_t)((wm * 32 + i * 16 + (lane & 15)) * 144
                                  + ks * 32 + (lane >> 4) * 16);
                    ldsm4(ah[i], addr);
                    if (TERMS >= 3) ldsm4(al[i], addr + APL);
                } else {
                    uint32_t addr = sb + (uint32_t)((ks * 16 + (lane & 15)) * 272
                                  + (wm * 32 + i * 16 + (lane >> 4) * 8) * 2);
                    uint32_t t[4];
                    ldsm4t(t, addr);
                    ah[i][0]=t[0]; ah[i][1]=t[2]; ah[i][2]=t[1]; ah[i][3]=t[3];
                    if (TERMS >= 3) {
                        ldsm4t(t, addr + APL);
                        al[i][0]=t[0]; al[i][1]=t[2]; al[i][2]=t[1]; al[i][3]=t[3];
                    }
                }
            }
#pragma unroll
            for (int i = 0; i < 2; i++)
#pragma unroll
                for (int j = 0; j < 4; j++) mma16816(acc[i][j], ah[i], bh[j]);
            if (TERMS >= 2) {
#pragma unroll
                for (int i = 0; i < 2; i++)
#pragma unroll
                    for (int j = 0; j < 4; j++) mma16816(acc[i][j], ah[i], bl[j]);
            }
            if (TERMS >= 3) {
#pragma unroll
                for (int i = 0; i < 2; i++)
#pragma unroll
                    for (int j = 0; j < 4; j++) mma16816(acc[i][j], al[i], bh[j]);
            }
        }
    };

    const int NC = K >> 6;
    issue(0, 0); cpa_commit();
    if (NC > 1) { issue(1, 1); cpa_commit(); }

    int st = 0;
    for (int i = 0; i < NC; i++) {
        if (i + 1 < NC) cpa_wait<1>(); else cpa_wait<0>();
        __syncthreads();
        if (i + 2 < NC) {
            int ns = st + 2; if (ns >= 3) ns -= 3;
            issue(i + 2, ns); cpa_commit();
        }
        compute(st);
        if (++st == 3) st = 0;
    }

    // ---- epilogue
    const int quad = lane >> 2, tq = lane & 3;
#pragma unroll
    for (int i = 0; i < 2; i++) {
#pragma unroll
        for (int h = 0; h < 2; h++) {
            int r = m0 + wm * 32 + i * 16 + quad + 8 * h;
            if (r >= Mstore) continue;
            float bv = 0.0f;
            if (ADD == 2) bv = bias[r];
#pragma unroll
            for (int j = 0; j < 4; j++) {
                int c = n0 + wn * 32 + j * 8 + tq * 2;
                float vx = acc[i][j][2 * h + 0];
                float vy = acc[i][j][2 * h + 1];
                if (ADD == 2) {
                    vx += bv; vy += bv;
                } else if (ADD == 3) {
                    size_t ao = sAux * (size_t)bz + (size_t)r * ldaux + c;
                    vx += __half2float(auxH[ao])   + __half2float(auxL[ao]);
                    vy += __half2float(auxH[ao+1]) + __half2float(auxL[ao+1]);
                }
                size_t off = sC * (size_t)bz + (size_t)(r - mofs) * ldc + c;
                if (PLANES) {
                    hlf hx, lx, hy, ly;
                    split1(vx, hx, lx); split1(vy, hy, ly);
                    *(uint32_t*)(CH + off) = pack2(hx, hy);
                    *(uint32_t*)(CL + off) = pack2(lx, ly);
                } else {
                    *(float2*)(Cf + off) = make_float2(vx, vy);
                }
            }
        }
    }
}

// ---------------------------------------------------------------------------
// Column softmax, smem-resident: attn [1023,1024] -> fp16 plane [1024,1024], row 1023 = 0
// ---------------------------------------------------------------------------
__global__ __launch_bounds__(256)
void softmax_col(const float* __restrict__ A, hlf* __restrict__ OH) {
    extern __shared__ float sv[];          // [1023][32]
    __shared__ float red[8][32];
    const int bz = blockIdx.z;
    const float* a = A + (size_t)bz * M_LEN * T_LEN;
    OH += (size_t)bz * D_MOD * T_LEN;
    const int tx = threadIdx.x, ty = threadIdx.y;
    const int col = blockIdx.x * 32 + tx;

    float mx = -INFINITY;
    for (int m = ty; m < M_LEN; m += 8) {
        float v = a[(size_t)m * T_LEN + col];
        sv[m * 32 + tx] = v;
        mx = fmaxf(mx, v);
    }
    red[ty][tx] = mx;
    __syncthreads();
    if (ty == 0) {
        float v = red[0][tx];
#pragma unroll
        for (int i = 1; i < 8; i++) v = fmaxf(v, red[i][tx]);
        red[0][tx] = v;
    }
    __syncthreads();
    mx = red[0][tx];
    __syncthreads();

    float s = 0.f;
    for (int m = ty; m < M_LEN; m += 8) {
        float e = expf(sv[m * 32 + tx] - mx);
        sv[m * 32 + tx] = e;
        s += e;
    }
    red[ty][tx] = s;
    __syncthreads();
    if (ty == 0) {
        float v = 0.f;
#pragma unroll
        for (int i = 0; i < 8; i++) v += red[i][tx];
        red[0][tx] = v;
    }
    __syncthreads();
    float inv = 1.0f / red[0][tx];

    for (int m = ty; m < M_LEN; m += 8)
        OH[(size_t)m * T_LEN + col] = __float2half(sv[m * 32 + tx] * inv);
    if (ty == 0)
        OH[(size_t)M_LEN * T_LEN + col] = __float2half(0.f);
}

// ---------------------------------------------------------------------------
// Launch
// ---------------------------------------------------------------------------
extern "C" void kernel_launch(void* const* d_in, const int* in_sizes, int n_in,
                              void* d_out, int out_size)
{
    const float* xs      = (const float*)d_in[0];
    const float* W_embed = (const float*)d_in[1];
    const float* W_KQ    = (const float*)d_in[2];
    const float* W_PV    = (const float*)d_in[3];
    const float* W_un    = (const float*)d_in[4];
    const float* b_un    = (const float*)d_in[5];

    float* out      = (float*)d_out;
    float* attn_out = out + (size_t)BATCH * D_IN * T_LEN;

#define SYM(p, s) cudaGetSymbolAddress((void**)&p, s)
    hlf *Xh,*Xl,*WAh,*WAl,*BWh,*BWl,*LLh,*LLl;
    hlf *O2h,*O2l,*O1bh,*O1bl,*URh,*URl,*Zh,*Zl,*Sh;
    SYM(Xh,g_Xh); SYM(Xl,g_Xl); SYM(WAh,g_WA2h); SYM(WAl,g_WA2l);
    SYM(BWh,g_BW2h); SYM(BWl,g_BW2l); SYM(LLh,g_LLh); SYM(LLl,g_LLl);
    SYM(O2h,g_O2h); SYM(O2l,g_O2l); SYM(O1bh,g_O1bh); SYM(O1bl,g_O1bl);
    SYM(URh,g_URh); SYM(URl,g_URl); SYM(Zh,g_Zh); SYM(Zl,g_Zl); SYM(Sh,g_Sh);

    constexpr int SMEM_N = 3 * (2 * 128 * 144 + 2 * 64 * 272);   // 215040
    constexpr int SMEM_T = 3 * (4 * 64 * 272);                   // 208896
    constexpr int SMEM_SM = M_LEN * 32 * 4;                      // 130944
    cudaFuncSetAttribute(mma_gemm<false,0,true ,3,false>, cudaFuncAttributeMaxDynamicSharedMemorySize, SMEM_N);
    cudaFuncSetAttribute(mma_gemm<true ,0,true ,3,true >, cudaFuncAttributeMaxDynamicSharedMemorySize, SMEM_T);
    cudaFuncSetAttribute(mma_gemm<false,3,true ,2,false>, cudaFuncAttributeMaxDynamicSharedMemorySize, SMEM_N);
    cudaFuncSetAttribute(mma_gemm<false,3,true ,1,false>, cudaFuncAttributeMaxDynamicSharedMemorySize, SMEM_N);
    cudaFuncSetAttribute(mma_gemm<true ,3,false,1,false>, cudaFuncAttributeMaxDynamicSharedMemorySize, SMEM_T);
    cudaFuncSetAttribute(mma_gemm<false,2,false,1,false>, cudaFuncAttributeMaxDynamicSharedMemorySize, SMEM_N);
    cudaFuncSetAttribute(softmax_col, cudaFuncAttributeMaxDynamicSharedMemorySize, SMEM_SM);

    const size_t sX    = (size_t)D_IN * T_LEN;      // 512K
    const size_t sS    = (size_t)D_MOD * T_LEN;     // 1M
    const size_t sUR   = (size_t)1536 * T_LEN;      // 1.5M
    const size_t sAttn = (size_t)M_LEN * T_LEN;

#define NOAUX nullptr, nullptr, 0, 0
#define NODUAL nullptr, nullptr, nullptr, nullptr, 0

    // ---- conversions
    conv_w<<<dim3(1024, 3), 256>>>((const float4*)W_KQ, (const float4*)W_PV,
                                   (const float4*)W_embed, WAh, WAl, BWh, BWl);
    tr_wun<<<dim3(32, 16), dim3(32, 8)>>>(W_un, BWh, BWl);
    {
        size_t n4 = (size_t)BATCH * sX / 4;
        conv_xs<<<(unsigned)((n4 + 255)/256), 256>>>((const float4*)xs, Xh, Xl, n4);
    }
    se_init<<<4096, 256>>>(BWh, BWl);

    // ---- L1: LL = [W_KQ; W_PV] @ BW2[:, 0:1536] = [O1top; H]   [2048,1536], K=1024
    mma_gemm<false,0,true,3,false><<<dim3(12,16,1), NT, SMEM_N>>>(WAh, WAl, BWh, BWl,
        nullptr, LLh, LLl, nullptr, NOAUX, NODUAL,
        1024, 1024, 2048, 1536, 2048, 0, 0, 0);
    // ---- L2 (DUAL, TA): A = BW2 [1024, 2048]
    //   m0 <  1536: O2  = BW^T    @ O1top  (cols 0-1535 of A)
    //   m0 >= 1536: O1b = W_un    @ H      (cols 1536-2047 of A = W_un^T)
    mma_gemm<true,0,true,3,true><<<dim3(12,16,1), NT, SMEM_T>>>(BWh, BWl, LLh, LLl,
        nullptr, O2h, O2l, nullptr, NOAUX,
        LLh + (size_t)1024*1536, LLl + (size_t)1024*1536, O1bh, O1bl, 1536,
        1024, 2048, 1536, 1536, 2048, 0, 0, 0);

    // ---- batched
    // [U'; R] = O2[:, :512] @ xs + O2[:, 512:]   (M=1536, K=512, 2-term)
    mma_gemm<false,3,true,2,false><<<dim3(8,12,BATCH), NT, SMEM_N>>>(O2h, O2l, Xh, Xl,
        nullptr, URh, URl, nullptr,
        O2h + 512, O2l + 512, 1536, 0, NODUAL,
        512, 1536, 1024, 1024, 1536, 0, sX, sUR);
    // Z = WcW @ xs + WcSE   (1-term)
    mma_gemm<false,3,true,1,false><<<dim3(8,4,BATCH), NT, SMEM_N>>>(O1bh, O1bl, Xh, Xl,
        nullptr, Zh, Zl, nullptr,
        O1bh + 512, O1bl + 512, 1536, 0, NODUAL,
        512, 1536, 1024, 1024, 512, 0, sX, sX);
    // attn = xs^T @ U' + R  -> fp32 d_out slice   (1-term; R full via aux)
    mma_gemm<true,3,false,1,false><<<dim3(8,8,BATCH), NT, SMEM_T>>>(Xh, Xh, URh, URh,
        attn_out, nullptr, nullptr, nullptr,
        URh + (size_t)512*1024, URl + (size_t)512*1024, 1024, sUR, NODUAL,
        512, 1024, 1024, 1024, M_LEN, sX, sUR, sAttn);
    // softmax -> Sh (single plane, row 1023 = 0)
    softmax_col<<<dim3(T_LEN/32, 1, BATCH), dim3(32, 8), SMEM_SM>>>(attn_out, Sh);
    // out = Z @ S + b_un  -> fp32 d_out slice     (1-term)
    mma_gemm<false,2,false,1,false><<<dim3(8,4,BATCH), NT, SMEM_N>>>(Zh, Zh, Sh, Sh,
        out, nullptr, nullptr, b_un, NOAUX, NODUAL,
        1024, 1024, 1024, 1024, 512, sX, sS, sX);
}

// round 15
// speedup vs baseline: 1.0292x; 1.0292x over previous
#include <cuda_runtime.h>
#include <cuda_fp16.h>
#include <math.h>
#include <stdint.h>

#define BATCH 32
#define D_IN  512
#define T_LEN 1024
#define D_MOD 1024
#define M_LEN 1023

#define SE_C (-8.99447308311468881e-03f)   // -ln(10000)/1024

typedef __half hlf;

// ---------------------------------------------------------------------------
// Scratch (allocation-free rule: __device__ globals), fp16 hi/lo planes
// ---------------------------------------------------------------------------
__device__ hlf g_Xh[(size_t)BATCH * D_IN * T_LEN];
__device__ hlf g_Xl[(size_t)BATCH * D_IN * T_LEN];
__device__ hlf g_WAh[1536 * D_MOD];                   // rows 0-1023 W_KQ, 1024-1535 Wc
__device__ hlf g_WAl[1536 * D_MOD];
__device__ hlf g_BWh[D_MOD * 1536];                   // [Wem | SE]
__device__ hlf g_BWl[D_MOD * 1536];
__device__ hlf g_Wpvh[D_MOD * D_MOD]; __device__ hlf g_Wpvl[D_MOD * D_MOD];
__device__ hlf g_Wunh[D_IN * D_MOD];  __device__ hlf g_Wunl[D_IN * D_MOD];
__device__ hlf g_O1h[1536 * 1536];                    // [Wke|KSE ; WcW|WcSE]
__device__ hlf g_O1l[1536 * 1536];
__device__ hlf g_O2h[1536 * 1536];                    // [Mw|P ; Q|V4]
__device__ hlf g_O2l[1536 * 1536];
__device__ hlf g_URh[(size_t)BATCH * 1536 * T_LEN];   // per batch: rows 0-511 U', 512-1535 R
__device__ hlf g_URl[(size_t)BATCH * 1536 * T_LEN];
__device__ hlf g_Zh[(size_t)BATCH * D_IN * T_LEN];
__device__ hlf g_Zl[(size_t)BATCH * D_IN * T_LEN];
__device__ hlf g_Sh[(size_t)BATCH * D_MOD * T_LEN];   // softmax (single plane, row 1023 = 0)

// ---------------------------------------------------------------------------
// Helpers
// ---------------------------------------------------------------------------
__device__ __forceinline__ uint32_t smem_u32(const void* p) {
    uint32_t a;
    asm("{ .reg .u64 t; cvta.to.shared.u64 t, %1; cvt.u32.u64 %0, t; }" : "=r"(a) : "l"(p));
    return a;
}
__device__ __forceinline__ void ldsm4(uint32_t* r, uint32_t addr) {
    asm volatile("ldmatrix.sync.aligned.m8n8.x4.shared.b16 {%0,%1,%2,%3}, [%4];"
        : "=r"(r[0]), "=r"(r[1]), "=r"(r[2]), "=r"(r[3]) : "r"(addr));
}
__device__ __forceinline__ void ldsm4t(uint32_t* r, uint32_t addr) {
    asm volatile("ldmatrix.sync.aligned.m8n8.x4.trans.shared.b16 {%0,%1,%2,%3}, [%4];"
        : "=r"(r[0]), "=r"(r[1]), "=r"(r[2]), "=r"(r[3]) : "r"(addr));
}
__device__ __forceinline__ void mma16816(float* d, const uint32_t* a, const uint32_t* b) {
    asm volatile("mma.sync.aligned.m16n8k16.row.col.f32.f16.f16.f32 "
        "{%0,%1,%2,%3}, {%4,%5,%6,%7}, {%8,%9}, {%0,%1,%2,%3};"
        : "+f"(d[0]), "+f"(d[1]), "+f"(d[2]), "+f"(d[3])
        : "r"(a[0]), "r"(a[1]), "r"(a[2]), "r"(a[3]), "r"(b[0]), "r"(b[1]));
}
__device__ __forceinline__ void cpa16(uint32_t dst, const void* src) {
    asm volatile("cp.async.cg.shared.global [%0], [%1], 16;" :: "r"(dst), "l"(src));
}
__device__ __forceinline__ void cpa_commit() {
    asm volatile("cp.async.commit_group;" ::: "memory");
}
template<int N>
__device__ __forceinline__ void cpa_wait() {
    asm volatile("cp.async.wait_group %0;" :: "n"(N) : "memory");
}
__device__ __forceinline__ uint32_t pack2(hlf a, hlf b) {
    __half2 t = __halves2half2(a, b);
    return *reinterpret_cast<uint32_t*>(&t);
}
__device__ __forceinline__ void split1(float x, hlf& h, hlf& l) {
    h = __float2half(x);
    l = __float2half(x - __half2float(h));
}

// ---------------------------------------------------------------------------
// One merged conversion kernel: range dispatch over a 1D grid of 256-thread blocks
//   [0,16384)      : xs split (4,194,304 float4)
//   [16384,17408)  : W_KQ  -> WA rows 0-1023
//   [17408,18432)  : W_PV
//   [18432,18944)  : W_un
//   [18944,19456)  : W_embed -> BW cols 0-511 (ld 1536)
//   [19456,23552)  : SE planes -> BW cols 512-1535
// ---------------------------------------------------------------------------
__device__ __forceinline__ void split_store4(float4 v, hlf* oh, hlf* ol, size_t off) {
    hlf h0,h1,h2,h3,l0,l1,l2,l3;
    split1(v.x,h0,l0); split1(v.y,h1,l1); split1(v.z,h2,l2); split1(v.w,h3,l3);
    *(uint2*)(oh + off) = make_uint2(pack2(h0,h1), pack2(h2,h3));
    *(uint2*)(ol + off) = make_uint2(pack2(l0,l1), pack2(l2,l3));
}

__global__ void conv_all(const float4* __restrict__ xs,
                         const float4* __restrict__ wkq, const float4* __restrict__ wpv,
                         const float4* __restrict__ wun, const float4* __restrict__ wem,
                         hlf* __restrict__ Xh, hlf* __restrict__ Xl,
                         hlf* __restrict__ WAh, hlf* __restrict__ WAl,
                         hlf* __restrict__ Wpvh, hlf* __restrict__ Wpvl,
                         hlf* __restrict__ Wunh, hlf* __restrict__ Wunl,
                         hlf* __restrict__ BWh,  hlf* __restrict__ BWl) {
    int b = blockIdx.x;
    int tid = threadIdx.x;
    if (b < 16384) {                                     // xs
        size_t i = (size_t)b * 256 + tid;
        split_store4(xs[i], Xh, Xl, 4 * i);
    } else if (b < 17408) {                              // W_KQ
        size_t i = (size_t)(b - 16384) * 256 + tid;
        split_store4(wkq[i], WAh, WAl, 4 * i);
    } else if (b < 18432) {                              // W_PV
        size_t i = (size_t)(b - 17408) * 256 + tid;
        split_store4(wpv[i], Wpvh, Wpvl, 4 * i);
    } else if (b < 18944) {                              // W_un
        size_t i = (size_t)(b - 18432) * 256 + tid;
        split_store4(wun[i], Wunh, Wunl, 4 * i);
    } else if (b < 19456) {                              // W_embed -> BW (ld 1536)
        size_t i = (size_t)(b - 18944) * 256 + tid;
        int r = (int)(i >> 7), c = ((int)i & 127) * 4;
        split_store4(wem[i], BWh, BWl, (size_t)r * 1536 + c);
    } else {                                             // SE -> BW cols 512-1535
        int idx = (b - 19456) * 256 + tid;
        int r = idx >> 10, c = idx & 1023;
        float freq = expf((float)(r & ~1) * SE_C);
        float ang  = (float)c * freq;
        float v = (r & 1) ? cosf(ang) : sinf(ang);
        hlf h, l; split1(v, h, l);
        size_t off = (size_t)r * 1536 + 512 + c;
        BWh[off] = h; BWl[off] = l;
    }
}

// ---------------------------------------------------------------------------
// MMA GEMM, fp16 planes, cp.async 3-stage pipeline, BK=64.
//   TERMS: 1 -> Ah*Bh;  2 -> + Ah*Bl;  3 -> + Al*Bh
//   TA=false: A [M,K]; TA=true: A [K,M]. B always [K,N].
//   ADD: 0 none, 2 += bias[r], 3 += (auxH+auxL)[r*ldaux+c]
//   PLANES: true -> CH/CL fp16 planes; false -> Cf fp32
// CTA 128x128, 512 threads, 16 warps (4x4), warp tile 32x32.
// ---------------------------------------------------------------------------
#define NT 512

template<bool TA, int ADD, bool PLANES, int TERMS>
__global__ __launch_bounds__(NT, 1)
void mma_gemm(const hlf* __restrict__ AH, const hlf* __restrict__ AL,
              const hlf* __restrict__ BH, const hlf* __restrict__ BL,
              float* __restrict__ Cf, hlf* __restrict__ CH, hlf* __restrict__ CL,
              const float* __restrict__ bias,
              const hlf* __restrict__ auxH, const hlf* __restrict__ auxL,
              int ldaux, size_t sAux,
              int K, int lda, int ldb, int ldc, int Mstore,
              size_t sA, size_t sB, size_t sC)
{
    constexpr int APL = TA ? (64 * 272) : (128 * 144);
    constexpr int BPL = 64 * 272;
    constexpr int SSZ = 2 * APL + 2 * BPL;
    extern __shared__ char smem[];

    const int tid = threadIdx.x, lane = tid & 31, wid = tid >> 5;
    const int wm = wid >> 2, wn = wid & 3;
    const int m0 = blockIdx.y * 128, n0 = blockIdx.x * 128, bz = blockIdx.z;
    AH += sA * (size_t)bz; AL += sA * (size_t)bz;
    BH += sB * (size_t)bz; BL += sB * (size_t)bz;
    const uint32_t sm = smem_u32(smem);

    float acc[2][4][4];
#pragma unroll
    for (int i = 0; i < 2; i++)
#pragma unroll
        for (int j = 0; j < 4; j++)
#pragma unroll
            for (int e = 0; e < 4; e++) acc[i][j][e] = 0.0f;

    auto issue = [&](int kc, int st) {
        uint32_t sb = sm + st * SSZ;
        int k0 = kc * 64;
        if (!TA) {
#pragma unroll
            for (int it = 0; it < 2; it++) {
                int idx = tid + it * NT;
                int r = idx >> 3, c = idx & 7;
                size_t go = (size_t)(m0 + r) * lda + k0 + c * 8;
                uint32_t so = sb + r * 144 + c * 16;
                cpa16(so, AH + go);
                if (TERMS >= 3) cpa16(so + APL, AL + go);
            }
        } else {
#pragma unroll
            for (int it = 0; it < 2; it++) {
                int idx = tid + it * NT;
                int r = idx >> 4, c = idx & 15;
                size_t go = (size_t)(k0 + r) * lda + m0 + c * 8;
                uint32_t so = sb + r * 272 + c * 16;
                cpa16(so, AH + go);
                if (TERMS >= 3) cpa16(so + APL, AL + go);
            }
        }
#pragma unroll
        for (int it = 0; it < 2; it++) {
            int idx = tid + it * NT;
            int r = idx >> 4, c = idx & 15;
            size_t go = (size_t)(k0 + r) * ldb + n0 + c * 8;
            uint32_t so = sb + 2 * APL + r * 272 + c * 16;
            cpa16(so, BH + go);
            if (TERMS >= 2) cpa16(so + BPL, BL + go);
        }
    };

    auto compute = [&](int st) {
        uint32_t sb = sm + st * SSZ;
#pragma unroll
        for (int ks = 0; ks < 4; ks++) {
            uint32_t ah[2][4], al[2][4], bh[4][2], bl[4][2];
#pragma unroll
            for (int j2 = 0; j2 < 2; j2++) {
                uint32_t addr = sb + 2 * APL + (uint32_t)((ks * 16 + (lane & 15)) * 272
                              + (wn * 32 + j2 * 16 + (lane >> 4) * 8) * 2);
                uint32_t t[4];
                ldsm4t(t, addr);
                bh[j2*2][0]=t[0]; bh[j2*2][1]=t[1]; bh[j2*2+1][0]=t[2]; bh[j2*2+1][1]=t[3];
                if (TERMS >= 2) {
                    ldsm4t(t, addr + BPL);
                    bl[j2*2][0]=t[0]; bl[j2*2][1]=t[1]; bl[j2*2+1][0]=t[2]; bl[j2*2+1][1]=t[3];
                }
            }
#pragma unroll
            for (int i = 0; i < 2; i++) {
                if (!TA) {
                    uint32_t addr = sb + (uint32_t)((wm * 32 + i * 16 + (lane & 15)) * 144
                                  + ks * 32 + (lane >> 4) * 16);
                    ldsm4(ah[i], addr);
                    if (TERMS >= 3) ldsm4(al[i], addr + APL);
                } else {
                    uint32_t addr = sb + (uint32_t)((ks * 16 + (lane & 15)) * 272
                                  + (wm * 32 + i * 16 + (lane >> 4) * 8) * 2);
                    uint32_t t[4];
                    ldsm4t(t, addr);
                    ah[i][0]=t[0]; ah[i][1]=t[2]; ah[i][2]=t[1]; ah[i][3]=t[3];
                    if (TERMS >= 3) {
                        ldsm4t(t, addr + APL);
                        al[i][0]=t[0]; al[i][1]=t[2]; al[i][2]=t[1]; al[i][3]=t[3];
                    }
                }
            }
#pragma unroll
            for (int i = 0; i < 2; i++)
#pragma unroll
                for (int j = 0; j < 4; j++) mma16816(acc[i][j], ah[i], bh[j]);
            if (TERMS >= 2) {
#pragma unroll
                for (int i = 0; i < 2; i++)
#pragma unroll
                    for (int j = 0; j < 4; j++) mma16816(acc[i][j], ah[i], bl[j]);
            }
            if (TERMS >= 3) {
#pragma unroll
                for (int i = 0; i < 2; i++)
#pragma unroll
                    for (int j = 0; j < 4; j++) mma16816(acc[i][j], al[i], bh[j]);
            }
        }
    };

    const int NC = K >> 6;
    issue(0, 0); cpa_commit();
    if (NC > 1) { issue(1, 1); cpa_commit(); }

    int st = 0;
    for (int i = 0; i < NC; i++) {
        if (i + 1 < NC) cpa_wait<1>(); else cpa_wait<0>();
        __syncthreads();
        if (i + 2 < NC) {
            int ns = st + 2; if (ns >= 3) ns -= 3;
            issue(i + 2, ns); cpa_commit();
        }
        compute(st);
        if (++st == 3) st = 0;
    }

    // ---- epilogue
    const int quad = lane >> 2, tq = lane & 3;
#pragma unroll
    for (int i = 0; i < 2; i++) {
#pragma unroll
        for (int h = 0; h < 2; h++) {
            int r = m0 + wm * 32 + i * 16 + quad + 8 * h;
            if (r >= Mstore) continue;
            float bv = 0.0f;
            if (ADD == 2) bv = bias[r];
#pragma unroll
            for (int j = 0; j < 4; j++) {
                int c = n0 + wn * 32 + j * 8 + tq * 2;
                float vx = acc[i][j][2 * h + 0];
                float vy = acc[i][j][2 * h + 1];
                if (ADD == 2) {
                    vx += bv; vy += bv;
                } else if (ADD == 3) {
                    size_t ao = sAux * (size_t)bz + (size_t)r * ldaux + c;
                    vx += __half2float(auxH[ao])   + __half2float(auxL[ao]);
                    vy += __half2float(auxH[ao+1]) + __half2float(auxL[ao+1]);
                }
                size_t off = sC * (size_t)bz + (size_t)r * ldc + c;
                if (PLANES) {
                    hlf hx, lx, hy, ly;
                    split1(vx, hx, lx); split1(vy, hy, ly);
                    *(uint32_t*)(CH + off) = pack2(hx, hy);
                    *(uint32_t*)(CL + off) = pack2(lx, ly);
                } else {
                    *(float2*)(Cf + off) = make_float2(vx, vy);
                }
            }
        }
    }
}

// ---------------------------------------------------------------------------
// Column softmax, smem-resident: attn [1023,1024] -> fp16 plane [1024,1024], row 1023 = 0
// ---------------------------------------------------------------------------
__global__ __launch_bounds__(256)
void softmax_col(const float* __restrict__ A, hlf* __restrict__ OH) {
    extern __shared__ float sv[];          // [1023][32]
    __shared__ float red[8][32];
    const int bz = blockIdx.z;
    const float* a = A + (size_t)bz * M_LEN * T_LEN;
    OH += (size_t)bz * D_MOD * T_LEN;
    const int tx = threadIdx.x, ty = threadIdx.y;
    const int col = blockIdx.x * 32 + tx;

    float mx = -INFINITY;
    for (int m = ty; m < M_LEN; m += 8) {
        float v = a[(size_t)m * T_LEN + col];
        sv[m * 32 + tx] = v;
        mx = fmaxf(mx, v);
    }
    red[ty][tx] = mx;
    __syncthreads();
    if (ty == 0) {
        float v = red[0][tx];
#pragma unroll
        for (int i = 1; i < 8; i++) v = fmaxf(v, red[i][tx]);
        red[0][tx] = v;
    }
    __syncthreads();
    mx = red[0][tx];
    __syncthreads();

    float s = 0.f;
    for (int m = ty; m < M_LEN; m += 8) {
        float e = expf(sv[m * 32 + tx] - mx);
        sv[m * 32 + tx] = e;
        s += e;
    }
    red[ty][tx] = s;
    __syncthreads();
    if (ty == 0) {
        float v = 0.f;
#pragma unroll
        for (int i = 0; i < 8; i++) v += red[i][tx];
        red[0][tx] = v;
    }
    __syncthreads();
    float inv = 1.0f / red[0][tx];

    for (int m = ty; m < M_LEN; m += 8)
        OH[(size_t)m * T_LEN + col] = __float2half(sv[m * 32 + tx] * inv);
    if (ty == 0)
        OH[(size_t)M_LEN * T_LEN + col] = __float2half(0.f);
}

// ---------------------------------------------------------------------------
// Launch
// ---------------------------------------------------------------------------
extern "C" void kernel_launch(void* const* d_in, const int* in_sizes, int n_in,
                              void* d_out, int out_size)
{
    const float* xs      = (const float*)d_in[0];
    const float* W_embed = (const float*)d_in[1];
    const float* W_KQ    = (const float*)d_in[2];
    const float* W_PV    = (const float*)d_in[3];
    const float* W_un    = (const float*)d_in[4];
    const float* b_un    = (const float*)d_in[5];

    float* out      = (float*)d_out;
    float* attn_out = out + (size_t)BATCH * D_IN * T_LEN;

#define SYM(p, s) cudaGetSymbolAddress((void**)&p, s)
    hlf *Xh,*Xl,*WAh,*WAl,*BWh,*BWl,*Wpvh,*Wpvl,*Wunh,*Wunl;
    hlf *O1h,*O1l,*O2h,*O2l,*URh,*URl,*Zh,*Zl,*Sh;
    SYM(Xh,g_Xh); SYM(Xl,g_Xl); SYM(WAh,g_WAh); SYM(WAl,g_WAl);
    SYM(BWh,g_BWh); SYM(BWl,g_BWl);
    SYM(Wpvh,g_Wpvh); SYM(Wpvl,g_Wpvl); SYM(Wunh,g_Wunh); SYM(Wunl,g_Wunl);
    SYM(O1h,g_O1h); SYM(O1l,g_O1l); SYM(O2h,g_O2h); SYM(O2l,g_O2l);
    SYM(URh,g_URh); SYM(URl,g_URl); SYM(Zh,g_Zh); SYM(Zl,g_Zl); SYM(Sh,g_Sh);

    constexpr int SMEM_N = 3 * (2 * 128 * 144 + 2 * 64 * 272);   // 215040
    constexpr int SMEM_T = 3 * (4 * 64 * 272);                   // 208896
    constexpr int SMEM_SM = M_LEN * 32 * 4;                      // 130944
    cudaFuncSetAttribute(mma_gemm<false,0,true ,3>, cudaFuncAttributeMaxDynamicSharedMemorySize, SMEM_N);
    cudaFuncSetAttribute(mma_gemm<true ,0,true ,3>, cudaFuncAttributeMaxDynamicSharedMemorySize, SMEM_T);
    cudaFuncSetAttribute(mma_gemm<false,3,true ,2>, cudaFuncAttributeMaxDynamicSharedMemorySize, SMEM_N);
    cudaFuncSetAttribute(mma_gemm<false,3,true ,1>, cudaFuncAttributeMaxDynamicSharedMemorySize, SMEM_N);
    cudaFuncSetAttribute(mma_gemm<true ,3,false,1>, cudaFuncAttributeMaxDynamicSharedMemorySize, SMEM_T);
    cudaFuncSetAttribute(mma_gemm<false,2,false,1>, cudaFuncAttributeMaxDynamicSharedMemorySize, SMEM_N);
    cudaFuncSetAttribute(softmax_col, cudaFuncAttributeMaxDynamicSharedMemorySize, SMEM_SM);

    const size_t sX    = (size_t)D_IN * T_LEN;      // 512K
    const size_t sS    = (size_t)D_MOD * T_LEN;     // 1M
    const size_t sUR   = (size_t)1536 * T_LEN;      // 1.5M
    const size_t sAttn = (size_t)M_LEN * T_LEN;

    // ---- all conversions in ONE launch (range dispatch)
    conv_all<<<23552, 256>>>((const float4*)xs,
                             (const float4*)W_KQ, (const float4*)W_PV,
                             (const float4*)W_un, (const float4*)W_embed,
                             Xh, Xl, WAh, WAl, Wpvh, Wpvl, Wunh, Wunl, BWh, BWl);

    // P1: Wc = W_un @ W_PV -> WA rows 1024-1535   (3-term)
    mma_gemm<false,0,true,3><<<dim3(8,4,1), NT, SMEM_N>>>(Wunh, Wunl, Wpvh, Wpvl,
        nullptr, WAh + (size_t)1024*1024, WAl + (size_t)1024*1024,
        nullptr, nullptr, nullptr, 0, 0,
        1024, 1024, 1024, 1024, 512, 0, 0, 0);
    // OUT1 = WA @ BW = [Wke|KSE ; WcW|WcSE]       (3-term)
    mma_gemm<false,0,true,3><<<dim3(12,12,1), NT, SMEM_N>>>(WAh, WAl, BWh, BWl,
        nullptr, O1h, O1l, nullptr, nullptr, nullptr, 0, 0,
        1024, 1024, 1536, 1536, 1536, 0, 0, 0);
    // OUT23 = BW^T @ OUT1[0:1024] = [Mw|P ; Q|V4] (3-term, TA — REVERTED from 2-term)
    mma_gemm<true,0,true,3><<<dim3(12,12,1), NT, SMEM_T>>>(BWh, BWl, O1h, O1l,
        nullptr, O2h, O2l, nullptr, nullptr, nullptr, 0, 0,
        1024, 1536, 1536, 1536, 1536, 0, 0, 0);
    // U' = Mw @ xs + P   (M=512, K=512, 2-term) -> UR rows 0-511
    mma_gemm<false,3,true,2><<<dim3(8,4,BATCH), NT, SMEM_N>>>(O2h, O2l, Xh, Xl,
        nullptr, URh, URl, nullptr,
        O2h + 512, O2l + 512, 1536, 0,
        512, 1536, 1024, 1024, 512, 0, sX, sUR);
    // R = Q @ xs + V4    (M=1024, K=512, 2-term) -> UR rows 512-1535
    mma_gemm<false,3,true,2><<<dim3(8,8,BATCH), NT, SMEM_N>>>(
        O2h + (size_t)512*1536, O2l + (size_t)512*1536, Xh, Xl,
        nullptr, URh + (size_t)512*1024, URl + (size_t)512*1024, nullptr,
        O2h + (size_t)512*1536 + 512, O2l + (size_t)512*1536 + 512, 1536, 0,
        512, 1536, 1024, 1024, 1024, 0, sX, sUR);
    // Z = WcW @ xs + WcSE   (1-term)
    mma_gemm<false,3,true,1><<<dim3(8,4,BATCH), NT, SMEM_N>>>(
        O1h + (size_t)1024*1536, O1l + (size_t)1024*1536, Xh, Xl,
        nullptr, Zh, Zl, nullptr,
        O1h + (size_t)1024*1536 + 512, O1l + (size_t)1024*1536 + 512, 1536, 0,
        512, 1536, 1024, 1024, 512, 0, sX, sX);
    // attn = xs^T @ U' + R  -> fp32 d_out slice   (1-term: xs_hi * U'_hi; R full via aux)
    mma_gemm<true,3,false,1><<<dim3(8,8,BATCH), NT, SMEM_T>>>(Xh, Xh, URh, URh,
        attn_out, nullptr, nullptr, nullptr,
        URh + (size_t)512*1024, URl + (size_t)512*1024, 1024, sUR,
        512, 1024, 1024, 1024, M_LEN, sX, sUR, sAttn);
    // softmax -> Sh (single plane, row 1023 = 0)
    softmax_col<<<dim3(T_LEN/32, 1, BATCH), dim3(32, 8), SMEM_SM>>>(attn_out, Sh);
    // out = Z @ S + b_un  -> fp32 d_out slice     (1-term)
    mma_gemm<false,2,false,1><<<dim3(8,4,BATCH), NT, SMEM_N>>>(Zh, Zh, Sh, Sh,
        out, nullptr, nullptr, b_un, nullptr, nullptr, 0, 0,
        1024, 1024, 1024, 1024, 512, sX, sS, sX);
}

// round 16
// speedup vs baseline: 1.0680x; 1.0377x over previous
#include <cuda_runtime.h>
#include <cuda_fp16.h>
#include <math.h>
#include <stdint.h>

#define BATCH 32
#define D_IN  512
#define T_LEN 1024
#define D_MOD 1024
#define M_LEN 1023

#define SE_C (-8.99447308311468881e-03f)   // -ln(10000)/1024

typedef __half hlf;

// ---------------------------------------------------------------------------
// Scratch (allocation-free rule: __device__ globals), fp16 hi/lo planes
// ---------------------------------------------------------------------------
__device__ hlf g_Xh[(size_t)BATCH * D_IN * T_LEN];
__device__ hlf g_Xl[(size_t)BATCH * D_IN * T_LEN];
__device__ hlf g_WAh[1536 * D_MOD];                   // rows 0-1023 W_KQ, 1024-1535 Wc
__device__ hlf g_WAl[1536 * D_MOD];
__device__ hlf g_BWh[D_MOD * 1536];                   // [Wem | SE]
__device__ hlf g_BWl[D_MOD * 1536];
__device__ hlf g_Wpvh[D_MOD * D_MOD]; __device__ hlf g_Wpvl[D_MOD * D_MOD];
__device__ hlf g_Wunh[D_IN * D_MOD];  __device__ hlf g_Wunl[D_IN * D_MOD];
__device__ hlf g_O1h[1536 * 1536];                    // [Wke|KSE ; WcW|WcSE]
__device__ hlf g_O1l[1536 * 1536];
__device__ hlf g_O2h[1536 * 1536];                    // [Mw|P ; Q|V4]
__device__ hlf g_O2l[1536 * 1536];
__device__ hlf g_URh[(size_t)BATCH * 1536 * T_LEN];   // per batch: rows 0-511 U', 512-1535 R
__device__ hlf g_URl[(size_t)BATCH * 1536 * T_LEN];
__device__ hlf g_Zh[(size_t)BATCH * D_IN * T_LEN];
__device__ hlf g_Zl[(size_t)BATCH * D_IN * T_LEN];
__device__ hlf g_Sh[(size_t)BATCH * D_MOD * T_LEN];   // softmax (single plane, row 1023 = 0)

// ---------------------------------------------------------------------------
// Helpers
// ---------------------------------------------------------------------------
__device__ __forceinline__ uint32_t smem_u32(const void* p) {
    uint32_t a;
    asm("{ .reg .u64 t; cvta.to.shared.u64 t, %1; cvt.u32.u64 %0, t; }" : "=r"(a) : "l"(p));
    return a;
}
__device__ __forceinline__ void ldsm4(uint32_t* r, uint32_t addr) {
    asm volatile("ldmatrix.sync.aligned.m8n8.x4.shared.b16 {%0,%1,%2,%3}, [%4];"
        : "=r"(r[0]), "=r"(r[1]), "=r"(r[2]), "=r"(r[3]) : "r"(addr));
}
__device__ __forceinline__ void ldsm4t(uint32_t* r, uint32_t addr) {
    asm volatile("ldmatrix.sync.aligned.m8n8.x4.trans.shared.b16 {%0,%1,%2,%3}, [%4];"
        : "=r"(r[0]), "=r"(r[1]), "=r"(r[2]), "=r"(r[3]) : "r"(addr));
}
__device__ __forceinline__ void mma16816(float* d, const uint32_t* a, const uint32_t* b) {
    asm volatile("mma.sync.aligned.m16n8k16.row.col.f32.f16.f16.f32 "
        "{%0,%1,%2,%3}, {%4,%5,%6,%7}, {%8,%9}, {%0,%1,%2,%3};"
        : "+f"(d[0]), "+f"(d[1]), "+f"(d[2]), "+f"(d[3])
        : "r"(a[0]), "r"(a[1]), "r"(a[2]), "r"(a[3]), "r"(b[0]), "r"(b[1]));
}
__device__ __forceinline__ void cpa16(uint32_t dst, const void* src) {
    asm volatile("cp.async.cg.shared.global [%0], [%1], 16;" :: "r"(dst), "l"(src));
}
__device__ __forceinline__ void cpa_commit() {
    asm volatile("cp.async.commit_group;" ::: "memory");
}
template<int N>
__device__ __forceinline__ void cpa_wait() {
    asm volatile("cp.async.wait_group %0;" :: "n"(N) : "memory");
}
__device__ __forceinline__ uint32_t pack2(hlf a, hlf b) {
    __half2 t = __halves2half2(a, b);
    return *reinterpret_cast<uint32_t*>(&t);
}
__device__ __forceinline__ void split1(float x, hlf& h, hlf& l) {
    h = __float2half(x);
    l = __float2half(x - __half2float(h));
}

// ---------------------------------------------------------------------------
// One merged conversion kernel: range dispatch over a 1D grid of 256-thread blocks
// ---------------------------------------------------------------------------
__device__ __forceinline__ void split_store4(float4 v, hlf* oh, hlf* ol, size_t off) {
    hlf h0,h1,h2,h3,l0,l1,l2,l3;
    split1(v.x,h0,l0); split1(v.y,h1,l1); split1(v.z,h2,l2); split1(v.w,h3,l3);
    *(uint2*)(oh + off) = make_uint2(pack2(h0,h1), pack2(h2,h3));
    *(uint2*)(ol + off) = make_uint2(pack2(l0,l1), pack2(l2,l3));
}

__global__ void conv_all(const float4* __restrict__ xs,
                         const float4* __restrict__ wkq, const float4* __restrict__ wpv,
                         const float4* __restrict__ wun, const float4* __restrict__ wem,
                         hlf* __restrict__ Xh, hlf* __restrict__ Xl,
                         hlf* __restrict__ WAh, hlf* __restrict__ WAl,
                         hlf* __restrict__ Wpvh, hlf* __restrict__ Wpvl,
                         hlf* __restrict__ Wunh, hlf* __restrict__ Wunl,
                         hlf* __restrict__ BWh,  hlf* __restrict__ BWl) {
    int b = blockIdx.x;
    int tid = threadIdx.x;
    if (b < 16384) {                                     // xs
        size_t i = (size_t)b * 256 + tid;
        split_store4(xs[i], Xh, Xl, 4 * i);
    } else if (b < 17408) {                              // W_KQ
        size_t i = (size_t)(b - 16384) * 256 + tid;
        split_store4(wkq[i], WAh, WAl, 4 * i);
    } else if (b < 18432) {                              // W_PV
        size_t i = (size_t)(b - 17408) * 256 + tid;
        split_store4(wpv[i], Wpvh, Wpvl, 4 * i);
    } else if (b < 18944) {                              // W_un
        size_t i = (size_t)(b - 18432) * 256 + tid;
        split_store4(wun[i], Wunh, Wunl, 4 * i);
    } else if (b < 19456) {                              // W_embed -> BW (ld 1536)
        size_t i = (size_t)(b - 18944) * 256 + tid;
        int r = (int)(i >> 7), c = ((int)i & 127) * 4;
        split_store4(wem[i], BWh, BWl, (size_t)r * 1536 + c);
    } else {                                             // SE -> BW cols 512-1535
        int idx = (b - 19456) * 256 + tid;
        int r = idx >> 10, c = idx & 1023;
        float freq = expf((float)(r & ~1) * SE_C);
        float ang  = (float)c * freq;
        float v = (r & 1) ? cosf(ang) : sinf(ang);
        hlf h, l; split1(v, h, l);
        size_t off = (size_t)r * 1536 + 512 + c;
        BWh[off] = h; BWl[off] = l;
    }
}

// ---------------------------------------------------------------------------
// MMA GEMM, fp16 planes, cp.async 3-stage pipeline, BK=64.
//   TERMS: 1 -> Ah*Bh;  2 -> + Ah*Bl;  3 -> + Al*Bh
//   TA=false: A [M,K]; TA=true: A [K,M]. B always [K,N].
//   ADD: 0 none, 2 += bias[r], 3 += (auxH+auxL)[r*ldaux+c]
//   PLANES: true -> CH/CL fp16 planes; false -> Cf fp32
// CTA 128x128, 512 threads, 16 warps (4x4), warp tile 32x32.
// ---------------------------------------------------------------------------
#define NT 512

template<bool TA, int ADD, bool PLANES, int TERMS>
__global__ __launch_bounds__(NT, 1)
void mma_gemm(const hlf* __restrict__ AH, const hlf* __restrict__ AL,
              const hlf* __restrict__ BH, const hlf* __restrict__ BL,
              float* __restrict__ Cf, hlf* __restrict__ CH, hlf* __restrict__ CL,
              const float* __restrict__ bias,
              const hlf* __restrict__ auxH, const hlf* __restrict__ auxL,
              int ldaux, size_t sAux,
              int K, int lda, int ldb, int ldc, int Mstore,
              size_t sA, size_t sB, size_t sC)
{
    constexpr int APL = TA ? (64 * 272) : (128 * 144);
    constexpr int BPL = 64 * 272;
    constexpr int SSZ = 2 * APL + 2 * BPL;
    extern __shared__ char smem[];

    const int tid = threadIdx.x, lane = tid & 31, wid = tid >> 5;
    const int wm = wid >> 2, wn = wid & 3;
    const int m0 = blockIdx.y * 128, n0 = blockIdx.x * 128, bz = blockIdx.z;
    AH += sA * (size_t)bz; AL += sA * (size_t)bz;
    BH += sB * (size_t)bz; BL += sB * (size_t)bz;
    const uint32_t sm = smem_u32(smem);

    float acc[2][4][4];
#pragma unroll
    for (int i = 0; i < 2; i++)
#pragma unroll
        for (int j = 0; j < 4; j++)
#pragma unroll
            for (int e = 0; e < 4; e++) acc[i][j][e] = 0.0f;

    auto issue = [&](int kc, int st) {
        uint32_t sb = sm + st * SSZ;
        int k0 = kc * 64;
        if (!TA) {
#pragma unroll
            for (int it = 0; it < 2; it++) {
                int idx = tid + it * NT;
                int r = idx >> 3, c = idx & 7;
                size_t go = (size_t)(m0 + r) * lda + k0 + c * 8;
                uint32_t so = sb + r * 144 + c * 16;
                cpa16(so, AH + go);
                if (TERMS >= 3) cpa16(so + APL, AL + go);
            }
        } else {
#pragma unroll
            for (int it = 0; it < 2; it++) {
                int idx = tid + it * NT;
                int r = idx >> 4, c = idx & 15;
                size_t go = (size_t)(k0 + r) * lda + m0 + c * 8;
                uint32_t so = sb + r * 272 + c * 16;
                cpa16(so, AH + go);
                if (TERMS >= 3) cpa16(so + APL, AL + go);
            }
        }
#pragma unroll
        for (int it = 0; it < 2; it++) {
            int idx = tid + it * NT;
            int r = idx >> 4, c = idx & 15;
            size_t go = (size_t)(k0 + r) * ldb + n0 + c * 8;
            uint32_t so = sb + 2 * APL + r * 272 + c * 16;
            cpa16(so, BH + go);
            if (TERMS >= 2) cpa16(so + BPL, BL + go);
        }
    };

    auto compute = [&](int st) {
        uint32_t sb = sm + st * SSZ;
#pragma unroll
        for (int ks = 0; ks < 4; ks++) {
            uint32_t ah[2][4], al[2][4], bh[4][2], bl[4][2];
#pragma unroll
            for (int j2 = 0; j2 < 2; j2++) {
                uint32_t addr = sb + 2 * APL + (uint32_t)((ks * 16 + (lane & 15)) * 272
                              + (wn * 32 + j2 * 16 + (lane >> 4) * 8) * 2);
                uint32_t t[4];
                ldsm4t(t, addr);
                bh[j2*2][0]=t[0]; bh[j2*2][1]=t[1]; bh[j2*2+1][0]=t[2]; bh[j2*2+1][1]=t[3];
                if (TERMS >= 2) {
                    ldsm4t(t, addr + BPL);
                    bl[j2*2][0]=t[0]; bl[j2*2][1]=t[1]; bl[j2*2+1][0]=t[2]; bl[j2*2+1][1]=t[3];
                }
            }
#pragma unroll
            for (int i = 0; i < 2; i++) {
                if (!TA) {
                    uint32_t addr = sb + (uint32_t)((wm * 32 + i * 16 + (lane & 15)) * 144
                                  + ks * 32 + (lane >> 4) * 16);
                    ldsm4(ah[i], addr);
                    if (TERMS >= 3) ldsm4(al[i], addr + APL);
                } else {
                    uint32_t addr = sb + (uint32_t)((ks * 16 + (lane & 15)) * 272
                                  + (wm * 32 + i * 16 + (lane >> 4) * 8) * 2);
                    uint32_t t[4];
                    ldsm4t(t, addr);
                    ah[i][0]=t[0]; ah[i][1]=t[2]; ah[i][2]=t[1]; ah[i][3]=t[3];
                    if (TERMS >= 3) {
                        ldsm4t(t, addr + APL);
                        al[i][0]=t[0]; al[i][1]=t[2]; al[i][2]=t[1]; al[i][3]=t[3];
                    }
                }
            }
#pragma unroll
            for (int i = 0; i < 2; i++)
#pragma unroll
                for (int j = 0; j < 4; j++) mma16816(acc[i][j], ah[i], bh[j]);
            if (TERMS >= 2) {
#pragma unroll
                for (int i = 0; i < 2; i++)
#pragma unroll
                    for (int j = 0; j < 4; j++) mma16816(acc[i][j], ah[i], bl[j]);
            }
            if (TERMS >= 3) {
#pragma unroll
                for (int i = 0; i < 2; i++)
#pragma unroll
                    for (int j = 0; j < 4; j++) mma16816(acc[i][j], al[i], bh[j]);
            }
        }
    };

    const int NC = K >> 6;
    issue(0, 0); cpa_commit();
    if (NC > 1) { issue(1, 1); cpa_commit(); }

    int st = 0;
    for (int i = 0; i < NC; i++) {
        if (i + 1 < NC) cpa_wait<1>(); else cpa_wait<0>();
        __syncthreads();
        if (i + 2 < NC) {
            int ns = st + 2; if (ns >= 3) ns -= 3;
            issue(i + 2, ns); cpa_commit();
        }
        compute(st);
        if (++st == 3) st = 0;
    }

    // ---- epilogue
    const int quad = lane >> 2, tq = lane & 3;
#pragma unroll
    for (int i = 0; i < 2; i++) {
#pragma unroll
        for (int h = 0; h < 2; h++) {
            int r = m0 + wm * 32 + i * 16 + quad + 8 * h;
            if (r >= Mstore) continue;
            float bv = 0.0f;
            if (ADD == 2) bv = bias[r];
#pragma unroll
            for (int j = 0; j < 4; j++) {
                int c = n0 + wn * 32 + j * 8 + tq * 2;
                float vx = acc[i][j][2 * h + 0];
                float vy = acc[i][j][2 * h + 1];
                if (ADD == 2) {
                    vx += bv; vy += bv;
                } else if (ADD == 3) {
                    size_t ao = sAux * (size_t)bz + (size_t)r * ldaux + c;
                    vx += __half2float(auxH[ao])   + __half2float(auxL[ao]);
                    vy += __half2float(auxH[ao+1]) + __half2float(auxL[ao+1]);
                }
                size_t off = sC * (size_t)bz + (size_t)r * ldc + c;
                if (PLANES) {
                    hlf hx, lx, hy, ly;
                    split1(vx, hx, lx); split1(vy, hy, ly);
                    *(uint32_t*)(CH + off) = pack2(hx, hy);
                    *(uint32_t*)(CL + off) = pack2(lx, ly);
                } else {
                    *(float2*)(Cf + off) = make_float2(vx, vy);
                }
            }
        }
    }
}

// ---------------------------------------------------------------------------
// Column softmax, smem-resident: attn [1023,1024] -> fp16 plane [1024,1024], row 1023 = 0
// ---------------------------------------------------------------------------
__global__ __launch_bounds__(256)
void softmax_col(const float* __restrict__ A, hlf* __restrict__ OH) {
    extern __shared__ float sv[];          // [1023][32]
    __shared__ float red[8][32];
    const int bz = blockIdx.z;
    const float* a = A + (size_t)bz * M_LEN * T_LEN;
    OH += (size_t)bz * D_MOD * T_LEN;
    const int tx = threadIdx.x, ty = threadIdx.y;
    const int col = blockIdx.x * 32 + tx;

    float mx = -INFINITY;
    for (int m = ty; m < M_LEN; m += 8) {
        float v = a[(size_t)m * T_LEN + col];
        sv[m * 32 + tx] = v;
        mx = fmaxf(mx, v);
    }
    red[ty][tx] = mx;
    __syncthreads();
    if (ty == 0) {
        float v = red[0][tx];
#pragma unroll
        for (int i = 1; i < 8; i++) v = fmaxf(v, red[i][tx]);
        red[0][tx] = v;
    }
    __syncthreads();
    mx = red[0][tx];
    __syncthreads();

    float s = 0.f;
    for (int m = ty; m < M_LEN; m += 8) {
        float e = expf(sv[m * 32 + tx] - mx);
        sv[m * 32 + tx] = e;
        s += e;
    }
    red[ty][tx] = s;
    __syncthreads();
    if (ty == 0) {
        float v = 0.f;
#pragma unroll
        for (int i = 0; i < 8; i++) v += red[i][tx];
        red[0][tx] = v;
    }
    __syncthreads();
    float inv = 1.0f / red[0][tx];

    for (int m = ty; m < M_LEN; m += 8)
        OH[(size_t)m * T_LEN + col] = __float2half(sv[m * 32 + tx] * inv);
    if (ty == 0)
        OH[(size_t)M_LEN * T_LEN + col] = __float2half(0.f);
}

// ---------------------------------------------------------------------------
// Launch: fork/join across a side stream so the P1 -> OUT1bot -> Z branch
// overlaps the OUT1top -> OUT23 -> UR -> attn -> softmax chain.
// Stream/events created once on the first (non-captured) correctness call.
// ---------------------------------------------------------------------------
extern "C" void kernel_launch(void* const* d_in, const int* in_sizes, int n_in,
                              void* d_out, int out_size)
{
    const float* xs      = (const float*)d_in[0];
    const float* W_embed = (const float*)d_in[1];
    const float* W_KQ    = (const float*)d_in[2];
    const float* W_PV    = (const float*)d_in[3];
    const float* W_un    = (const float*)d_in[4];
    const float* b_un    = (const float*)d_in[5];

    float* out      = (float*)d_out;
    float* attn_out = out + (size_t)BATCH * D_IN * T_LEN;

#define SYM(p, s) cudaGetSymbolAddress((void**)&p, s)
    hlf *Xh,*Xl,*WAh,*WAl,*BWh,*BWl,*Wpvh,*Wpvl,*Wunh,*Wunl;
    hlf *O1h,*O1l,*O2h,*O2l,*URh,*URl,*Zh,*Zl,*Sh;
    SYM(Xh,g_Xh); SYM(Xl,g_Xl); SYM(WAh,g_WAh); SYM(WAl,g_WAl);
    SYM(BWh,g_BWh); SYM(BWl,g_BWl);
    SYM(Wpvh,g_Wpvh); SYM(Wpvl,g_Wpvl); SYM(Wunh,g_Wunh); SYM(Wunl,g_Wunl);
    SYM(O1h,g_O1h); SYM(O1l,g_O1l); SYM(O2h,g_O2h); SYM(O2l,g_O2l);
    SYM(URh,g_URh); SYM(URl,g_URl); SYM(Zh,g_Zh); SYM(Zl,g_Zl); SYM(Sh,g_Sh);

    constexpr int SMEM_N = 3 * (2 * 128 * 144 + 2 * 64 * 272);   // 215040
    constexpr int SMEM_T = 3 * (4 * 64 * 272);                   // 208896
    constexpr int SMEM_SM = M_LEN * 32 * 4;                      // 130944
    cudaFuncSetAttribute(mma_gemm<false,0,true ,3>, cudaFuncAttributeMaxDynamicSharedMemorySize, SMEM_N);
    cudaFuncSetAttribute(mma_gemm<true ,0,true ,3>, cudaFuncAttributeMaxDynamicSharedMemorySize, SMEM_T);
    cudaFuncSetAttribute(mma_gemm<false,3,true ,2>, cudaFuncAttributeMaxDynamicSharedMemorySize, SMEM_N);
    cudaFuncSetAttribute(mma_gemm<false,3,true ,1>, cudaFuncAttributeMaxDynamicSharedMemorySize, SMEM_N);
    cudaFuncSetAttribute(mma_gemm<true ,3,false,1>, cudaFuncAttributeMaxDynamicSharedMemorySize, SMEM_T);
    cudaFuncSetAttribute(mma_gemm<false,2,false,1>, cudaFuncAttributeMaxDynamicSharedMemorySize, SMEM_N);
    cudaFuncSetAttribute(softmax_col, cudaFuncAttributeMaxDynamicSharedMemorySize, SMEM_SM);

    const size_t sX    = (size_t)D_IN * T_LEN;      // 512K
    const size_t sS    = (size_t)D_MOD * T_LEN;     // 1M
    const size_t sUR   = (size_t)1536 * T_LEN;      // 1.5M
    const size_t sAttn = (size_t)M_LEN * T_LEN;

    // one-time side stream + fork/join events (created on the non-captured
    // correctness call; replayed graph contains only the launches/edges)
    static cudaStream_t s_side = nullptr;
    static cudaEvent_t  s_fork = nullptr, s_join = nullptr;
    if (s_side == nullptr) {
        cudaStreamCreateWithFlags(&s_side, cudaStreamNonBlocking);
        cudaEventCreateWithFlags(&s_fork, cudaEventDisableTiming);
        cudaEventCreateWithFlags(&s_join, cudaEventDisableTiming);
    }

    // ---- all conversions in ONE launch (main stream)
    conv_all<<<23552, 256>>>((const float4*)xs,
                             (const float4*)W_KQ, (const float4*)W_PV,
                             (const float4*)W_un, (const float4*)W_embed,
                             Xh, Xl, WAh, WAl, Wpvh, Wpvl, Wunh, Wunl, BWh, BWl);
    cudaEventRecord(s_fork, 0);
    cudaStreamWaitEvent(s_side, s_fork, 0);

    // ======== SIDE BRANCH: P1 -> OUT1bot -> Z ========
    // P1: Wc = W_un @ W_PV -> WA rows 1024-1535   (3-term)
    mma_gemm<false,0,true,3><<<dim3(8,4,1), NT, SMEM_N, s_side>>>(Wunh, Wunl, Wpvh, Wpvl,
        nullptr, WAh + (size_t)1024*1024, WAl + (size_t)1024*1024,
        nullptr, nullptr, nullptr, 0, 0,
        1024, 1024, 1024, 1024, 512, 0, 0, 0);
    // OUT1bot: [WcW|WcSE] = Wc @ BW -> O1 rows 1024-1535   (3-term)
    mma_gemm<false,0,true,3><<<dim3(12,4,1), NT, SMEM_N, s_side>>>(
        WAh + (size_t)1024*1024, WAl + (size_t)1024*1024, BWh, BWl,
        nullptr, O1h + (size_t)1024*1536, O1l + (size_t)1024*1536,
        nullptr, nullptr, nullptr, 0, 0,
        1024, 1024, 1536, 1536, 512, 0, 0, 0);
    // Z = WcW @ xs + WcSE   (1-term, batched)
    mma_gemm<false,3,true,1><<<dim3(8,4,BATCH), NT, SMEM_N, s_side>>>(
        O1h + (size_t)1024*1536, O1l + (size_t)1024*1536, Xh, Xl,
        nullptr, Zh, Zl, nullptr,
        O1h + (size_t)1024*1536 + 512, O1l + (size_t)1024*1536 + 512, 1536, 0,
        512, 1536, 1024, 1024, 512, 0, sX, sX);
    cudaEventRecord(s_join, s_side);

    // ======== MAIN BRANCH ========
    // OUT1top: [Wke|KSE] = W_KQ @ BW -> O1 rows 0-1023   (3-term)
    mma_gemm<false,0,true,3><<<dim3(12,8,1), NT, SMEM_N>>>(WAh, WAl, BWh, BWl,
        nullptr, O1h, O1l, nullptr, nullptr, nullptr, 0, 0,
        1024, 1024, 1536, 1536, 1024, 0, 0, 0);
    // OUT23 = BW^T @ OUT1top = [Mw|P ; Q|V4]   (3-term, TA)
    mma_gemm<true,0,true,3><<<dim3(12,12,1), NT, SMEM_T>>>(BWh, BWl, O1h, O1l,
        nullptr, O2h, O2l, nullptr, nullptr, nullptr, 0, 0,
        1024, 1536, 1536, 1536, 1536, 0, 0, 0);
    // U' = Mw @ xs + P   (M=512, K=512, 2-term) -> UR rows 0-511
    mma_gemm<false,3,true,2><<<dim3(8,4,BATCH), NT, SMEM_N>>>(O2h, O2l, Xh, Xl,
        nullptr, URh, URl, nullptr,
        O2h + 512, O2l + 512, 1536, 0,
        512, 1536, 1024, 1024, 512, 0, sX, sUR);
    // R = Q @ xs + V4    (M=1024, K=512, 2-term) -> UR rows 512-1535
    mma_gemm<false,3,true,2><<<dim3(8,8,BATCH), NT, SMEM_N>>>(
        O2h + (size_t)512*1536, O2l + (size_t)512*1536, Xh, Xl,
        nullptr, URh + (size_t)512*1024, URl + (size_t)512*1024, nullptr,
        O2h + (size_t)512*1536 + 512, O2l + (size_t)512*1536 + 512, 1536, 0,
        512, 1536, 1024, 1024, 1024, 0, sX, sUR);
    // attn = xs^T @ U' + R  -> fp32 d_out slice   (1-term; R full via aux)
    mma_gemm<true,3,false,1><<<dim3(8,8,BATCH), NT, SMEM_T>>>(Xh, Xh, URh, URh,
        attn_out, nullptr, nullptr, nullptr,
        URh + (size_t)512*1024, URl + (size_t)512*1024, 1024, sUR,
        512, 1024, 1024, 1024, M_LEN, sX, sUR, sAttn);
    // softmax -> Sh (single plane, row 1023 = 0)
    softmax_col<<<dim3(T_LEN/32, 1, BATCH), dim3(32, 8), SMEM_SM>>>(attn_out, Sh);

    // join: out needs Z (side) + Sh (main)
    cudaStreamWaitEvent(0, s_join, 0);
    // out = Z @ S + b_un  -> fp32 d_out slice     (1-term)
    mma_gemm<false,2,false,1><<<dim3(8,4,BATCH), NT, SMEM_N>>>(Zh, Zh, Sh, Sh,
        out, nullptr, nullptr, b_un, nullptr, nullptr, 0, 0,
        1024, 1024, 1024, 1024, 512, sX, sS, sX);
}

// round 17
// speedup vs baseline: 1.0806x; 1.0118x over previous
#include <cuda_runtime.h>
#include <cuda_fp16.h>
#include <math.h>
#include <stdint.h>

#define BATCH 32
#define D_IN  512
#define T_LEN 1024
#define D_MOD 1024
#define M_LEN 1023

#define SE_C (-8.99447308311468881e-03f)   // -ln(10000)/1024

typedef __half hlf;

// ---------------------------------------------------------------------------
// Scratch (allocation-free rule: __device__ globals), fp16 hi/lo planes
// ---------------------------------------------------------------------------
__device__ hlf g_Xh[(size_t)BATCH * D_IN * T_LEN];
__device__ hlf g_Xl[(size_t)BATCH * D_IN * T_LEN];
__device__ hlf g_WAh[1536 * D_MOD];                   // rows 0-1023 W_KQ, 1024-1535 Wc
__device__ hlf g_WAl[1536 * D_MOD];
__device__ hlf g_BWh[D_MOD * 1536];                   // [Wem | SE]
__device__ hlf g_BWl[D_MOD * 1536];
__device__ hlf g_Wpvh[D_MOD * D_MOD]; __device__ hlf g_Wpvl[D_MOD * D_MOD];
__device__ hlf g_Wunh[D_IN * D_MOD];  __device__ hlf g_Wunl[D_IN * D_MOD];
__device__ hlf g_O1h[1536 * 1536];                    // [Wke|KSE ; WcW|WcSE]
__device__ hlf g_O1l[1536 * 1536];
__device__ hlf g_O2h[1536 * 1536];                    // [Mw|P ; Q|V4]
__device__ hlf g_O2l[1536 * 1536];
__device__ hlf g_URh[(size_t)BATCH * 1536 * T_LEN];   // per batch: rows 0-511 U', 512-1535 R
__device__ hlf g_URl[(size_t)BATCH * 1536 * T_LEN];
__device__ hlf g_Zh[(size_t)BATCH * D_IN * T_LEN];
__device__ hlf g_Zl[(size_t)BATCH * D_IN * T_LEN];
__device__ hlf g_Sh[(size_t)BATCH * D_MOD * T_LEN];   // softmax (single plane, row 1023 = 0)

// ---------------------------------------------------------------------------
// Helpers
// ---------------------------------------------------------------------------
__device__ __forceinline__ uint32_t smem_u32(const void* p) {
    uint32_t a;
    asm("{ .reg .u64 t; cvta.to.shared.u64 t, %1; cvt.u32.u64 %0, t; }" : "=r"(a) : "l"(p));
    return a;
}
__device__ __forceinline__ void ldsm4(uint32_t* r, uint32_t addr) {
    asm volatile("ldmatrix.sync.aligned.m8n8.x4.shared.b16 {%0,%1,%2,%3}, [%4];"
        : "=r"(r[0]), "=r"(r[1]), "=r"(r[2]), "=r"(r[3]) : "r"(addr));
}
__device__ __forceinline__ void ldsm4t(uint32_t* r, uint32_t addr) {
    asm volatile("ldmatrix.sync.aligned.m8n8.x4.trans.shared.b16 {%0,%1,%2,%3}, [%4];"
        : "=r"(r[0]), "=r"(r[1]), "=r"(r[2]), "=r"(r[3]) : "r"(addr));
}
__device__ __forceinline__ void mma16816(float* d, const uint32_t* a, const uint32_t* b) {
    asm volatile("mma.sync.aligned.m16n8k16.row.col.f32.f16.f16.f32 "
        "{%0,%1,%2,%3}, {%4,%5,%6,%7}, {%8,%9}, {%0,%1,%2,%3};"
        : "+f"(d[0]), "+f"(d[1]), "+f"(d[2]), "+f"(d[3])
        : "r"(a[0]), "r"(a[1]), "r"(a[2]), "r"(a[3]), "r"(b[0]), "r"(b[1]));
}
__device__ __forceinline__ void cpa16(uint32_t dst, const void* src) {
    asm volatile("cp.async.cg.shared.global [%0], [%1], 16;" :: "r"(dst), "l"(src));
}
__device__ __forceinline__ void cpa_commit() {
    asm volatile("cp.async.commit_group;" ::: "memory");
}
template<int N>
__device__ __forceinline__ void cpa_wait() {
    asm volatile("cp.async.wait_group %0;" :: "n"(N) : "memory");
}
__device__ __forceinline__ uint32_t pack2(hlf a, hlf b) {
    __half2 t = __halves2half2(a, b);
    return *reinterpret_cast<uint32_t*>(&t);
}
__device__ __forceinline__ void split1(float x, hlf& h, hlf& l) {
    h = __float2half(x);
    l = __float2half(x - __half2float(h));
}

// ---------------------------------------------------------------------------
// One merged conversion kernel: range dispatch over a 1D grid of 256-thread blocks
// ---------------------------------------------------------------------------
__device__ __forceinline__ void split_store4(float4 v, hlf* oh, hlf* ol, size_t off) {
    hlf h0,h1,h2,h3,l0,l1,l2,l3;
    split1(v.x,h0,l0); split1(v.y,h1,l1); split1(v.z,h2,l2); split1(v.w,h3,l3);
    *(uint2*)(oh + off) = make_uint2(pack2(h0,h1), pack2(h2,h3));
    *(uint2*)(ol + off) = make_uint2(pack2(l0,l1), pack2(l2,l3));
}

__global__ void conv_all(const float4* __restrict__ xs,
                         const float4* __restrict__ wkq, const float4* __restrict__ wpv,
                         const float4* __restrict__ wun, const float4* __restrict__ wem,
                         hlf* __restrict__ Xh, hlf* __restrict__ Xl,
                         hlf* __restrict__ WAh, hlf* __restrict__ WAl,
                         hlf* __restrict__ Wpvh, hlf* __restrict__ Wpvl,
                         hlf* __restrict__ Wunh, hlf* __restrict__ Wunl,
                         hlf* __restrict__ BWh,  hlf* __restrict__ BWl) {
    int b = blockIdx.x;
    int tid = threadIdx.x;
    if (b < 16384) {                                     // xs
        size_t i = (size_t)b * 256 + tid;
        split_store4(xs[i], Xh, Xl, 4 * i);
    } else if (b < 17408) {                              // W_KQ
        size_t i = (size_t)(b - 16384) * 256 + tid;
        split_store4(wkq[i], WAh, WAl, 4 * i);
    } else if (b < 18432) {                              // W_PV
        size_t i = (size_t)(b - 17408) * 256 + tid;
        split_store4(wpv[i], Wpvh, Wpvl, 4 * i);
    } else if (b < 18944) {                              // W_un
        size_t i = (size_t)(b - 18432) * 256 + tid;
        split_store4(wun[i], Wunh, Wunl, 4 * i);
    } else if (b < 19456) {                              // W_embed -> BW (ld 1536)
        size_t i = (size_t)(b - 18944) * 256 + tid;
        int r = (int)(i >> 7), c = ((int)i & 127) * 4;
        split_store4(wem[i], BWh, BWl, (size_t)r * 1536 + c);
    } else {                                             // SE -> BW cols 512-1535
        int idx = (b - 19456) * 256 + tid;
        int r = idx >> 10, c = idx & 1023;
        float freq = expf((float)(r & ~1) * SE_C);
        float ang  = (float)c * freq;
        float v = (r & 1) ? cosf(ang) : sinf(ang);
        hlf h, l; split1(v, h, l);
        size_t off = (size_t)r * 1536 + 512 + c;
        BWh[off] = h; BWl[off] = l;
    }
}

// ---------------------------------------------------------------------------
// MMA GEMM, fp16 planes, cp.async pipeline with TERMS-aware stage layout.
//   TERMS: 1 -> Ah*Bh;  2 -> + Ah*Bl;  3 -> + Al*Bh
//   Stage planes: A_hi @0 [, A_lo @APL if T>=3]; B_hi @ASZ [, B_lo @ASZ+BPL if T>=2]
//   Pipeline depth: T==1 -> 5 stages, T==2 -> 4, T==3 -> 3.
//   TA=false: A [M,K]; TA=true: A [K,M]. B always [K,N].
//   ADD: 0 none, 2 += bias[r], 3 += (auxH+auxL)[r*ldaux+c]
//   PLANES: true -> CH/CL fp16 planes; false -> Cf fp32
// CTA 128x128, 512 threads, 16 warps (4x4), warp tile 32x32.
// ---------------------------------------------------------------------------
#define NT 512

template<bool TA, int ADD, bool PLANES, int TERMS>
__global__ __launch_bounds__(NT, 1)
void mma_gemm(const hlf* __restrict__ AH, const hlf* __restrict__ AL,
              const hlf* __restrict__ BH, const hlf* __restrict__ BL,
              float* __restrict__ Cf, hlf* __restrict__ CH, hlf* __restrict__ CL,
              const float* __restrict__ bias,
              const hlf* __restrict__ auxH, const hlf* __restrict__ auxL,
              int ldaux, size_t sAux,
              int K, int lda, int ldb, int ldc, int Mstore,
              size_t sA, size_t sB, size_t sC)
{
    constexpr int APL  = TA ? (64 * 272) : (128 * 144);
    constexpr int BPL  = 64 * 272;
    constexpr int ASZ  = (TERMS >= 3 ? 2 : 1) * APL;
    constexpr int SSZ  = ASZ + (TERMS >= 2 ? 2 : 1) * BPL;
    constexpr int NSTG = (TERMS == 1) ? 5 : (TERMS == 2 ? 4 : 3);
    extern __shared__ char smem[];

    const int tid = threadIdx.x, lane = tid & 31, wid = tid >> 5;
    const int wm = wid >> 2, wn = wid & 3;
    const int m0 = blockIdx.y * 128, n0 = blockIdx.x * 128, bz = blockIdx.z;
    AH += sA * (size_t)bz; AL += sA * (size_t)bz;
    BH += sB * (size_t)bz; BL += sB * (size_t)bz;
    const uint32_t sm = smem_u32(smem);

    float acc[2][4][4];
#pragma unroll
    for (int i = 0; i < 2; i++)
#pragma unroll
        for (int j = 0; j < 4; j++)
#pragma unroll
            for (int e = 0; e < 4; e++) acc[i][j][e] = 0.0f;

    auto issue = [&](int kc, int st) {
        uint32_t sb = sm + st * SSZ;
        int k0 = kc * 64;
        if (!TA) {
#pragma unroll
            for (int it = 0; it < 2; it++) {
                int idx = tid + it * NT;
                int r = idx >> 3, c = idx & 7;
                size_t go = (size_t)(m0 + r) * lda + k0 + c * 8;
                uint32_t so = sb + r * 144 + c * 16;
                cpa16(so, AH + go);
                if (TERMS >= 3) cpa16(so + APL, AL + go);
            }
        } else {
#pragma unroll
            for (int it = 0; it < 2; it++) {
                int idx = tid + it * NT;
                int r = idx >> 4, c = idx & 15;
                size_t go = (size_t)(k0 + r) * lda + m0 + c * 8;
                uint32_t so = sb + r * 272 + c * 16;
                cpa16(so, AH + go);
                if (TERMS >= 3) cpa16(so + APL, AL + go);
            }
        }
#pragma unroll
        for (int it = 0; it < 2; it++) {
            int idx = tid + it * NT;
            int r = idx >> 4, c = idx & 15;
            size_t go = (size_t)(k0 + r) * ldb + n0 + c * 8;
            uint32_t so = sb + ASZ + r * 272 + c * 16;
            cpa16(so, BH + go);
            if (TERMS >= 2) cpa16(so + BPL, BL + go);
        }
    };

    auto compute = [&](int st) {
        uint32_t sb = sm + st * SSZ;
#pragma unroll
        for (int ks = 0; ks < 4; ks++) {
            uint32_t ah[2][4], al[2][4], bh[4][2], bl[4][2];
#pragma unroll
            for (int j2 = 0; j2 < 2; j2++) {
                uint32_t addr = sb + ASZ + (uint32_t)((ks * 16 + (lane & 15)) * 272
                              + (wn * 32 + j2 * 16 + (lane >> 4) * 8) * 2);
                uint32_t t[4];
                ldsm4t(t, addr);
                bh[j2*2][0]=t[0]; bh[j2*2][1]=t[1]; bh[j2*2+1][0]=t[2]; bh[j2*2+1][1]=t[3];
                if (TERMS >= 2) {
                    ldsm4t(t, addr + BPL);
                    bl[j2*2][0]=t[0]; bl[j2*2][1]=t[1]; bl[j2*2+1][0]=t[2]; bl[j2*2+1][1]=t[3];
                }
            }
#pragma unroll
            for (int i = 0; i < 2; i++) {
                if (!TA) {
                    uint32_t addr = sb + (uint32_t)((wm * 32 + i * 16 + (lane & 15)) * 144
                                  + ks * 32 + (lane >> 4) * 16);
                    ldsm4(ah[i], addr);
                    if (TERMS >= 3) ldsm4(al[i], addr + APL);
                } else {
                    uint32_t addr = sb + (uint32_t)((ks * 16 + (lane & 15)) * 272
                                  + (wm * 32 + i * 16 + (lane >> 4) * 8) * 2);
                    uint32_t t[4];
                    ldsm4t(t, addr);
                    ah[i][0]=t[0]; ah[i][1]=t[2]; ah[i][2]=t[1]; ah[i][3]=t[3];
                    if (TERMS >= 3) {
                        ldsm4t(t, addr + APL);
                        al[i][0]=t[0]; al[i][1]=t[2]; al[i][2]=t[1]; al[i][3]=t[3];
                    }
                }
            }
#pragma unroll
            for (int i = 0; i < 2; i++)
#pragma unroll
                for (int j = 0; j < 4; j++) mma16816(acc[i][j], ah[i], bh[j]);
            if (TERMS >= 2) {
#pragma unroll
                for (int i = 0; i < 2; i++)
#pragma unroll
                    for (int j = 0; j < 4; j++) mma16816(acc[i][j], ah[i], bl[j]);
            }
            if (TERMS >= 3) {
#pragma unroll
                for (int i = 0; i < 2; i++)
#pragma unroll
                    for (int j = 0; j < 4; j++) mma16816(acc[i][j], al[i], bh[j]);
            }
        }
    };

    const int NC = K >> 6;
    // prologue: prefetch up to NSTG-1 chunks (one commit group per stage slot)
#pragma unroll
    for (int p = 0; p < NSTG - 1; p++) {
        if (p < NC) issue(p, p);
        cpa_commit();
    }

    int st = 0;
    for (int i = 0; i < NC; i++) {
        cpa_wait<NSTG - 2>();
        __syncthreads();
        {
            int nc = i + NSTG - 1;
            if (nc < NC) {
                int ns = st + NSTG - 1; if (ns >= NSTG) ns -= NSTG;
                issue(nc, ns);
            }
            cpa_commit();
        }
        compute(st);
        if (++st == NSTG) st = 0;
    }

    // ---- epilogue
    const int quad = lane >> 2, tq = lane & 3;
#pragma unroll
    for (int i = 0; i < 2; i++) {
#pragma unroll
        for (int h = 0; h < 2; h++) {
            int r = m0 + wm * 32 + i * 16 + quad + 8 * h;
            if (r >= Mstore) continue;
            float bv = 0.0f;
            if (ADD == 2) bv = bias[r];
#pragma unroll
            for (int j = 0; j < 4; j++) {
                int c = n0 + wn * 32 + j * 8 + tq * 2;
                float vx = acc[i][j][2 * h + 0];
                float vy = acc[i][j][2 * h + 1];
                if (ADD == 2) {
                    vx += bv; vy += bv;
                } else if (ADD == 3) {
                    size_t ao = sAux * (size_t)bz + (size_t)r * ldaux + c;
                    vx += __half2float(auxH[ao])   + __half2float(auxL[ao]);
                    vy += __half2float(auxH[ao+1]) + __half2float(auxL[ao+1]);
                }
                size_t off = sC * (size_t)bz + (size_t)r * ldc + c;
                if (PLANES) {
                    hlf hx, lx, hy, ly;
                    split1(vx, hx, lx); split1(vy, hy, ly);
                    *(uint32_t*)(CH + off) = pack2(hx, hy);
                    *(uint32_t*)(CL + off) = pack2(lx, ly);
                } else {
                    *(float2*)(Cf + off) = make_float2(vx, vy);
                }
            }
        }
    }
}

// ---------------------------------------------------------------------------
// Column softmax, smem-resident: attn [1023,1024] -> fp16 plane [1024,1024], row 1023 = 0
// ---------------------------------------------------------------------------
__global__ __launch_bounds__(256)
void softmax_col(const float* __restrict__ A, hlf* __restrict__ OH) {
    extern __shared__ float sv[];          // [1023][32]
    __shared__ float red[8][32];
    const int bz = blockIdx.z;
    const float* a = A + (size_t)bz * M_LEN * T_LEN;
    OH += (size_t)bz * D_MOD * T_LEN;
    const int tx = threadIdx.x, ty = threadIdx.y;
    const int col = blockIdx.x * 32 + tx;

    float mx = -INFINITY;
    for (int m = ty; m < M_LEN; m += 8) {
        float v = a[(size_t)m * T_LEN + col];
        sv[m * 32 + tx] = v;
        mx = fmaxf(mx, v);
    }
    red[ty][tx] = mx;
    __syncthreads();
    if (ty == 0) {
        float v = red[0][tx];
#pragma unroll
        for (int i = 1; i < 8; i++) v = fmaxf(v, red[i][tx]);
        red[0][tx] = v;
    }
    __syncthreads();
    mx = red[0][tx];
    __syncthreads();

    float s = 0.f;
    for (int m = ty; m < M_LEN; m += 8) {
        float e = expf(sv[m * 32 + tx] - mx);
        sv[m * 32 + tx] = e;
        s += e;
    }
    red[ty][tx] = s;
    __syncthreads();
    if (ty == 0) {
        float v = 0.f;
#pragma unroll
        for (int i = 0; i < 8; i++) v += red[i][tx];
        red[0][tx] = v;
    }
    __syncthreads();
    float inv = 1.0f / red[0][tx];

    for (int m = ty; m < M_LEN; m += 8)
        OH[(size_t)m * T_LEN + col] = __float2half(sv[m * 32 + tx] * inv);
    if (ty == 0)
        OH[(size_t)M_LEN * T_LEN + col] = __float2half(0.f);
}

// ---------------------------------------------------------------------------
// Launch: fork/join across a side stream (P1 -> OUT1bot -> Z overlaps main chain)
// ---------------------------------------------------------------------------
extern "C" void kernel_launch(void* const* d_in, const int* in_sizes, int n_in,
                              void* d_out, int out_size)
{
    const float* xs      = (const float*)d_in[0];
    const float* W_embed = (const float*)d_in[1];
    const float* W_KQ    = (const float*)d_in[2];
    const float* W_PV    = (const float*)d_in[3];
    const float* W_un    = (const float*)d_in[4];
    const float* b_un    = (const float*)d_in[5];

    float* out      = (float*)d_out;
    float* attn_out = out + (size_t)BATCH * D_IN * T_LEN;

#define SYM(p, s) cudaGetSymbolAddress((void**)&p, s)
    hlf *Xh,*Xl,*WAh,*WAl,*BWh,*BWl,*Wpvh,*Wpvl,*Wunh,*Wunl;
    hlf *O1h,*O1l,*O2h,*O2l,*URh,*URl,*Zh,*Zl,*Sh;
    SYM(Xh,g_Xh); SYM(Xl,g_Xl); SYM(WAh,g_WAh); SYM(WAl,g_WAl);
    SYM(BWh,g_BWh); SYM(BWl,g_BWl);
    SYM(Wpvh,g_Wpvh); SYM(Wpvl,g_Wpvl); SYM(Wunh,g_Wunh); SYM(Wunl,g_Wunl);
    SYM(O1h,g_O1h); SYM(O1l,g_O1l); SYM(O2h,g_O2h); SYM(O2l,g_O2l);
    SYM(URh,g_URh); SYM(URl,g_URl); SYM(Zh,g_Zh); SYM(Zl,g_Zl); SYM(Sh,g_Sh);

    // per-instantiation dynamic smem sizes
    constexpr int SM_N3 = 3 * (2*128*144 + 2*64*272);   // 215040
    constexpr int SM_T3 = 3 * (2*64*272  + 2*64*272);   // 208896
    constexpr int SM_N2 = 4 * (128*144 + 2*64*272);     // 212992
    constexpr int SM_N1 = 5 * (128*144 + 64*272);       // 179200
    constexpr int SM_T1 = 5 * (64*272  + 64*272);       // 174080
    constexpr int SMEM_SM = M_LEN * 32 * 4;             // 130944
    cudaFuncSetAttribute(mma_gemm<false,0,true ,3>, cudaFuncAttributeMaxDynamicSharedMemorySize, SM_N3);
    cudaFuncSetAttribute(mma_gemm<true ,0,true ,3>, cudaFuncAttributeMaxDynamicSharedMemorySize, SM_T3);
    cudaFuncSetAttribute(mma_gemm<false,3,true ,2>, cudaFuncAttributeMaxDynamicSharedMemorySize, SM_N2);
    cudaFuncSetAttribute(mma_gemm<false,3,true ,1>, cudaFuncAttributeMaxDynamicSharedMemorySize, SM_N1);
    cudaFuncSetAttribute(mma_gemm<true ,3,false,1>, cudaFuncAttributeMaxDynamicSharedMemorySize, SM_T1);
    cudaFuncSetAttribute(mma_gemm<false,2,false,1>, cudaFuncAttributeMaxDynamicSharedMemorySize, SM_N1);
    cudaFuncSetAttribute(softmax_col, cudaFuncAttributeMaxDynamicSharedMemorySize, SMEM_SM);

    const size_t sX    = (size_t)D_IN * T_LEN;      // 512K
    const size_t sS    = (size_t)D_MOD * T_LEN;     // 1M
    const size_t sUR   = (size_t)1536 * T_LEN;      // 1.5M
    const size_t sAttn = (size_t)M_LEN * T_LEN;

    static cudaStream_t s_side = nullptr;
    static cudaEvent_t  s_fork = nullptr, s_join = nullptr;
    if (s_side == nullptr) {
        cudaStreamCreateWithFlags(&s_side, cudaStreamNonBlocking);
        cudaEventCreateWithFlags(&s_fork, cudaEventDisableTiming);
        cudaEventCreateWithFlags(&s_join, cudaEventDisableTiming);
    }

    // ---- all conversions in ONE launch (main stream)
    conv_all<<<23552, 256>>>((const float4*)xs,
                             (const float4*)W_KQ, (const float4*)W_PV,
                             (const float4*)W_un, (const float4*)W_embed,
                             Xh, Xl, WAh, WAl, Wpvh, Wpvl, Wunh, Wunl, BWh, BWl);
    cudaEventRecord(s_fork, 0);
    cudaStreamWaitEvent(s_side, s_fork, 0);

    // ======== SIDE BRANCH: P1 -> OUT1bot -> Z ========
    mma_gemm<false,0,true,3><<<dim3(8,4,1), NT, SM_N3, s_side>>>(Wunh, Wunl, Wpvh, Wpvl,
        nullptr, WAh + (size_t)1024*1024, WAl + (size_t)1024*1024,
        nullptr, nullptr, nullptr, 0, 0,
        1024, 1024, 1024, 1024, 512, 0, 0, 0);
    mma_gemm<false,0,true,3><<<dim3(12,4,1), NT, SM_N3, s_side>>>(
        WAh + (size_t)1024*1024, WAl + (size_t)1024*1024, BWh, BWl,
        nullptr, O1h + (size_t)1024*1536, O1l + (size_t)1024*1536,
        nullptr, nullptr, nullptr, 0, 0,
        1024, 1024, 1536, 1536, 512, 0, 0, 0);
    mma_gemm<false,3,true,1><<<dim3(8,4,BATCH), NT, SM_N1, s_side>>>(
        O1h + (size_t)1024*1536, O1l + (size_t)1024*1536, Xh, Xl,
        nullptr, Zh, Zl, nullptr,
        O1h + (size_t)1024*1536 + 512, O1l + (size_t)1024*1536 + 512, 1536, 0,
        512, 1536, 1024, 1024, 512, 0, sX, sX);
    cudaEventRecord(s_join, s_side);

    // ======== MAIN BRANCH ========
    mma_gemm<false,0,true,3><<<dim3(12,8,1), NT, SM_N3>>>(WAh, WAl, BWh, BWl,
        nullptr, O1h, O1l, nullptr, nullptr, nullptr, 0, 0,
        1024, 1024, 1536, 1536, 1024, 0, 0, 0);
    mma_gemm<true,0,true,3><<<dim3(12,12,1), NT, SM_T3>>>(BWh, BWl, O1h, O1l,
        nullptr, O2h, O2l, nullptr, nullptr, nullptr, 0, 0,
        1024, 1536, 1536, 1536, 1536, 0, 0, 0);
    mma_gemm<false,3,true,2><<<dim3(8,4,BATCH), NT, SM_N2>>>(O2h, O2l, Xh, Xl,
        nullptr, URh, URl, nullptr,
        O2h + 512, O2l + 512, 1536, 0,
        512, 1536, 1024, 1024, 512, 0, sX, sUR);
    mma_gemm<false,3,true,2><<<dim3(8,8,BATCH), NT, SM_N2>>>(
        O2h + (size_t)512*1536, O2l + (size_t)512*1536, Xh, Xl,
        nullptr, URh + (size_t)512*1024, URl + (size_t)512*1024, nullptr,
        O2h + (size_t)512*1536 + 512, O2l + (size_t)512*1536 + 512, 1536, 0,
        512, 1536, 1024, 1024, 1024, 0, sX, sUR);
    mma_gemm<true,3,false,1><<<dim3(8,8,BATCH), NT, SM_T1>>>(Xh, Xh, URh, URh,
        attn_out, nullptr, nullptr, nullptr,
        URh + (size_t)512*1024, URl + (size_t)512*1024, 1024, sUR,
        512, 1024, 1024, 1024, M_LEN, sX, sUR, sAttn);
    softmax_col<<<dim3(T_LEN/32, 1, BATCH), dim3(32, 8), SMEM_SM>>>(attn_out, Sh);

    // join: out needs Z (side) + Sh (main)
    cudaStreamWaitEvent(0, s_join, 0);
    mma_gemm<false,2,false,1><<<dim3(8,4,BATCH), NT, SM_N1>>>(Zh, Zh, Sh, Sh,
        out, nullptr, nullptr, b_un, nullptr, nullptr, 0, 0,
        1024, 1024, 1024, 1024, 512, sX, sS, sX);
}